// round 12
// baseline (speedup 1.0000x reference)
#include <cuda_runtime.h>
#include <math.h>
#include <stdint.h>

typedef uint32_t u32;

// ---------------- scratch (device globals; no allocation) ----------------
__device__ float g_latT [256*256];
__device__ float g_craw [256*1536];
__device__ float g_x1raw[2][256*2048];
__device__ float g_y2   [2][256*256*31];
__device__ float g_abc  [2][512];
__device__ float g_abhw [2][2][128];
__device__ float g_ab2  [2][2][256];
__device__ float g_hw   [2][256*512*32];
// int8 dual-digit fragment-order operands + per-row/col scales
__device__ __align__(16) u32 g_A2q1[2][256*4*32*4], g_A2q0[2][256*4*32*4];
__device__ __align__(16) u32 g_B2q1[2][512*4*32*2], g_B2q0[2][512*4*32*2];
__device__ __align__(16) u32 g_A3q1[2][512*8*32*4], g_A3q0[2][512*8*32*4];
__device__ __align__(16) u32 g_B3q1[2][128*8*32*2], g_B3q0[2][128*8*32*2];
__device__ float g_sA2[2][4096];
__device__ float g_tB2[2][4096];
__device__ float g_sA3[2][8192];
__device__ float g_tB3[2][1024];

__device__ __forceinline__ void wreduce2(float& s, float& q) {
    #pragma unroll
    for (int o = 16; o > 0; o >>= 1) {
        s += __shfl_xor_sync(0xffffffffu, s, o);
        q += __shfl_xor_sync(0xffffffffu, q, o);
    }
}

#define MMAS8(c, a, b) \
    asm volatile("mma.sync.aligned.m16n8k32.row.col.s32.s8.s8.s32 " \
                 "{%0,%1,%2,%3}, {%4,%5,%6,%7}, {%8,%9}, {%0,%1,%2,%3};" \
                 : "+r"((c)[0]), "+r"((c)[1]), "+r"((c)[2]), "+r"((c)[3]) \
                 : "r"((a)[0]), "r"((a)[1]), "r"((a)[2]), "r"((a)[3]), \
                   "r"((b)[0]), "r"((b)[1]))

// quantize x to two s8 digits: x ~= s*(128*d1 + d0), q = x/s in [-16256,16256]
#define QUANT_PACK(VAL, INV, P1, P0, J) do { \
    int q_ = __float2int_rn((VAL) * (INV)); \
    int d1_ = (q_ + 64) >> 7; \
    int d0_ = q_ - (d1_ << 7); \
    P1 |= (u32)(d1_ & 0xff) << (8*(J)); \
    P0 |= (u32)(d0_ & 0xff) << (8*(J)); \
} while(0)

extern __shared__ float dynf[];

// ---------------- kernel 1: latent + prepW2 + prepW3 combo ----------------
__global__ __launch_bounds__(256) void k_combo(
    const float* __restrict__ noise, const int* __restrict__ label,
    const float* __restrict__ lin_w, const float* __restrict__ bn0_g,
    const float* __restrict__ bn0_b, const float* __restrict__ emb,
    const float* __restrict__ W2h, const float* __restrict__ W2w,
    const float* __restrict__ W3h, const float* __restrict__ W3w)
{
    const int bid = blockIdx.x, tid = threadIdx.x;
    __shared__ float invt[64];
    if (bid < 256) {
        // ---- latent ----
        const int ch = bid, b = tid;
        if (ch >= 128) {
            g_latT[ch*256 + b] = emb[label[b]*128 + (ch - 128)];
            return;
        }
        __shared__ float wsm[100];
        if (b < 100) wsm[b] = lin_w[ch*100 + b];
        __syncthreads();
        const float* nr = noise + b*100;
        float z = 0.f;
        #pragma unroll 4
        for (int i = 0; i < 100; i++) z += nr[i]*wsm[i];
        float s = z, q = z*z;
        wreduce2(s, q);
        __shared__ float sp[8], qp[8];
        if ((b & 31) == 0) { sp[b >> 5] = s; qp[b >> 5] = q; }
        __syncthreads();
        float ts = 0.f, tq = 0.f;
        #pragma unroll
        for (int i = 0; i < 8; i++) { ts += sp[i]; tq += qp[i]; }
        float m   = ts*(1.f/256.f);
        float var = tq*(1.f/256.f) - m*m;
        float a   = bn0_g[ch]*rsqrtf(var + 1e-5f);
        float y   = (z - m)*a + bn0_b[ch];
        g_latT[ch*256 + b] = (y >= 0.f) ? y : 0.01f*y;
        return;
    }
    if (bid < 384) {
        // ---- prepW2: quantize W2 into B2 fragment order ----
        int idx = bid - 256, br = idx >> 6, n0 = (idx & 63)*64;
        const float* __restrict__ W = br ? W2w : W2h;   // [128 ci][4096 n]
        float* ts = dynf;                                // [128][65]
        for (int i = tid; i < 8192; i += 256) {
            int ci = i >> 6, nn = i & 63;
            ts[ci*65 + nn] = W[ci*4096 + n0 + nn];
        }
        __syncthreads();
        if (tid < 64) {
            float m = 0.f;
            for (int ci = 0; ci < 128; ci++) m = fmaxf(m, fabsf(ts[ci*65 + tid]));
            g_tB2[br][n0 + tid] = m * (1.f/16256.f);
            invt[tid] = (m > 0.f) ? 16256.f/m : 0.f;
        }
        __syncthreads();
        for (int it = 0; it < 8; it++) {
            int widx = tid + it*256;            // 0..2047
            int nl = widx >> 5, rem = widx & 31;
            int ks = rem >> 3, w = (rem >> 2) & 1, qt = rem & 3;
            float inv = invt[nl];
            u32 p1 = 0, p0 = 0;
            #pragma unroll
            for (int j = 0; j < 4; j++) {
                int ci = ks*32 + w*16 + qt*4 + j;
                QUANT_PACK(ts[ci*65 + nl], inv, p1, p0, j);
            }
            int n = n0 + nl;
            int ln = (n & 7)*4 + qt;
            int addr = (((n >> 3)*4 + ks)*32 + ln)*2 + w;
            g_B2q1[br][addr] = p1;
            g_B2q0[br][addr] = p0;
        }
        return;
    }
    // ---- prepW3 ----
    {
        int idx = bid - 384, br = idx >> 4, n0 = (idx & 15)*64;
        const float* __restrict__ W = br ? W3w : W3h;   // [256 ci][1024 n]
        float* ts = dynf;                                // [256][65]
        for (int i = tid; i < 16384; i += 256) {
            int ci = i >> 6, nn = i & 63;
            ts[ci*65 + nn] = W[ci*1024 + n0 + nn];
        }
        __syncthreads();
        if (tid < 64) {
            float m = 0.f;
            for (int ci = 0; ci < 256; ci++) m = fmaxf(m, fabsf(ts[ci*65 + tid]));
            g_tB3[br][n0 + tid] = m * (1.f/16256.f);
            invt[tid] = (m > 0.f) ? 16256.f/m : 0.f;
        }
        __syncthreads();
        for (int it = 0; it < 16; it++) {
            int widx = tid + it*256;            // 0..4095
            int nl = widx >> 6, rem = widx & 63;
            int ks = rem >> 3, w = (rem >> 2) & 1, qt = rem & 3;
            float inv = invt[nl];
            u32 p1 = 0, p0 = 0;
            #pragma unroll
            for (int j = 0; j < 4; j++) {
                int ci = ks*32 + w*16 + qt*4 + j;
                QUANT_PACK(ts[ci*65 + nl], inv, p1, p0, j);
            }
            int n = n0 + nl;
            int ln = (n & 7)*4 + qt;
            int addr = (((n >> 3)*8 + ks)*32 + ln)*2 + w;
            g_B3q1[br][addr] = p1;
            g_B3q0[br][addr] = p0;
        }
    }
}

// ---------------- kernel 2: conv1 GEMMs, all branches (raw) ----------------
__global__ __launch_bounds__(256) void k_gemm1m(
    const float* __restrict__ Wc, const float* __restrict__ Wh,
    const float* __restrict__ Ww)
{
    const int z = blockIdx.z;
    int N; const float* W; float* O;
    if (z == 2) {
        if (blockIdx.x >= 24) return;
        N = 1536; W = Wc; O = g_craw;
    } else {
        N = 2048; W = z ? Ww : Wh; O = g_x1raw[z];
    }
    const int n0 = blockIdx.x*64, b0 = blockIdx.y*64;
    const int tid = threadIdx.x, tx = tid & 15, ty = tid >> 4;
    __shared__ float Xs[16][68], Ws[16][68];
    float acc[4][4] = {};
    for (int k0 = 0; k0 < 256; k0 += 16) {
        __syncthreads();
        for (int i = tid; i < 1024; i += 256) {
            int k = i >> 6, c = i & 63;
            Xs[k][c] = g_latT[(k0+k)*256 + b0 + c];
            Ws[k][c] = W[(k0+k)*N + n0 + c];
        }
        __syncthreads();
        #pragma unroll
        for (int k = 0; k < 16; k++) {
            float4 x4 = *(const float4*)&Xs[k][ty*4];
            float4 w4 = *(const float4*)&Ws[k][tx*4];
            float xa[4] = {x4.x, x4.y, x4.z, x4.w};
            float wa[4] = {w4.x, w4.y, w4.z, w4.w};
            #pragma unroll
            for (int i = 0; i < 4; i++)
                #pragma unroll
                for (int j = 0; j < 4; j++) acc[i][j] += xa[i]*wa[j];
        }
    }
    #pragma unroll
    for (int i = 0; i < 4; i++) {
        float4 v = make_float4(acc[i][0], acc[i][1], acc[i][2], acc[i][3]);
        *(float4*)&O[(b0 + ty*4 + i)*N + n0 + tx*4] = v;
    }
}

// ---------------- kernel 3: BN stats conv1 ----------------
__global__ __launch_bounds__(256) void k_bnstats1(
    const float* __restrict__ cg, const float* __restrict__ cb,
    const float* __restrict__ hg, const float* __restrict__ hb,
    const float* __restrict__ wg, const float* __restrict__ wb)
{
    const int bid = blockIdx.x, b = threadIdx.x;
    float s = 0.f, q = 0.f; float invn; float gam, bet;
    int which, br = 0, co;
    if (bid < 512) {
        which = 0; co = bid;
        const float* p = g_craw + b*1536 + co*3;
        #pragma unroll
        for (int l = 0; l < 3; l++) { float v = p[l]; s += v; q += v*v; }
        invn = 1.f/(256.f*3.f); gam = cg[co]; bet = cb[co];
    } else {
        which = 1; int idx = bid - 512; br = idx >> 7; co = idx & 127;
        const float* p = g_x1raw[br] + b*2048 + co*16;
        #pragma unroll
        for (int l = 0; l < 16; l++) { float v = p[l]; s += v; q += v*v; }
        invn = 1.f/(256.f*16.f);
        gam = br ? wg[co] : hg[co]; bet = br ? wb[co] : hb[co];
    }
    wreduce2(s, q);
    __shared__ float sp[8], qp[8];
    if ((b & 31) == 0) { sp[b >> 5] = s; qp[b >> 5] = q; }
    __syncthreads();
    if (b == 0) {
        float ts = 0.f, tq = 0.f;
        #pragma unroll
        for (int i = 0; i < 8; i++) { ts += sp[i]; tq += qp[i]; }
        float m   = ts*invn;
        float var = tq*invn - m*m;
        float a   = gam*rsqrtf(var + 1e-5f);
        float sh  = bet - m*a;
        if (which == 0) { g_abc[0][co] = a; g_abc[1][co] = sh; }
        else            { g_abhw[br][0][co] = a; g_abhw[br][1][co] = sh; }
    }
}

// ---------------- prepA2: BN+lrelu, row amax, quantize to fragment order ----------
__global__ __launch_bounds__(256) void k_prepA2q()
{
    const int b = blockIdx.x, br = blockIdx.y, tid = threadIdx.x;
    const int lane = tid & 31, wrp = tid >> 5;
    __shared__ float xs[128*17];
    __shared__ float aAs[128], aSs[128];
    __shared__ float invs[16];
    if (tid < 128) { aAs[tid] = g_abhw[br][0][tid]; aSs[tid] = g_abhw[br][1][tid]; }
    __syncthreads();
    for (int idx = tid; idx < 2048; idx += 256) {
        int ci = idx >> 4, l = idx & 15;
        float v = g_x1raw[br][b*2048 + idx];
        v = fmaf(aAs[ci], v, aSs[ci]);
        v = (v >= 0.f) ? v : 0.2f*v;
        xs[ci*17 + l] = v;
    }
    __syncthreads();
    #pragma unroll
    for (int rr = 0; rr < 2; rr++) {
        int l = wrp*2 + rr;
        float m = 0.f;
        #pragma unroll
        for (int c4 = 0; c4 < 4; c4++) m = fmaxf(m, fabsf(xs[(lane + c4*32)*17 + l]));
        #pragma unroll
        for (int o = 16; o > 0; o >>= 1) m = fmaxf(m, __shfl_xor_sync(0xffffffffu, m, o));
        if (lane == 0) {
            g_sA2[br][b*16 + l] = m * (1.f/16256.f);
            invs[l] = (m > 0.f) ? 16256.f/m : 0.f;
        }
    }
    __syncthreads();
    #pragma unroll
    for (int it = 0; it < 2; it++) {
        int widx = tid + it*256;        // 0..511
        int ks = widx >> 7, rem = widx & 127;
        int ln = rem >> 2, w = rem & 3;
        int qr = ln >> 2, qt = ln & 3;
        int r = ((w & 1) << 3) | qr;
        int kb = ((w >> 1) << 4) | (qt << 2);
        float inv = invs[r];
        u32 p1 = 0, p0 = 0;
        #pragma unroll
        for (int j = 0; j < 4; j++) {
            int ci = ks*32 + kb + j;
            QUANT_PACK(xs[ci*17 + r], inv, p1, p0, j);
        }
        int addr = ((b*4 + ks)*32 + ln)*4 + w;
        g_A2q1[br][addr] = p1;
        g_A2q0[br][addr] = p0;
    }
}

// ---------------- conv2: int8 dual-digit mma.sync ----------------
extern __shared__ u32 smw[];
__global__ __launch_bounds__(256, 2) void k_conv2q()
{
    const int br = blockIdx.z, nx = blockIdx.x, my = blockIdx.y;
    const int tid = threadIdx.x, lane = tid & 31, wid = tid >> 5;
    const int wm = wid >> 2, wn = wid & 3;
    const int qr = lane >> 2, qt = lane & 3;
    __shared__ float sAs[128], tBs[128];
    if (tid < 128) sAs[tid] = g_sA2[br][my*128 + tid] * 128.f;
    else           tBs[tid-128] = g_tB2[br][nx*128 + (tid-128)];
    const u32* __restrict__ A1 = g_A2q1[br];
    const u32* __restrict__ A0 = g_A2q0[br];
    const u32* __restrict__ B1 = g_B2q1[br];
    const u32* __restrict__ B0 = g_B2q0[br];
    const int mi0 = my*8 + wm*4;
    float* Cs = (float*)smw;                    // 128 x 132 fp32
    __syncthreads();
    #pragma unroll
    for (int half = 0; half < 4; half++) {
        const int ni = nx*16 + wn*4 + half;
        int c11[4][4] = {}, cm[4][4] = {};
        #pragma unroll
        for (int ks = 0; ks < 4; ks++) {
            int ba = ((ni*4 + ks)*32 + lane)*2;
            uint2 b1v = *(const uint2*)(B1 + ba);
            uint2 b0v = *(const uint2*)(B0 + ba);
            u32 b1r[2] = {b1v.x, b1v.y};
            u32 b0r[2] = {b0v.x, b0v.y};
            #pragma unroll
            for (int mt = 0; mt < 4; mt++) {
                int aa = (((mi0+mt)*4 + ks)*32 + lane)*4;
                uint4 a1v = *(const uint4*)(A1 + aa);
                uint4 a0v = *(const uint4*)(A0 + aa);
                u32 a1r[4] = {a1v.x, a1v.y, a1v.z, a1v.w};
                u32 a0r[4] = {a0v.x, a0v.y, a0v.z, a0v.w};
                MMAS8(c11[mt], a1r, b1r);
                MMAS8(cm[mt],  a1r, b0r);
                MMAS8(cm[mt],  a0r, b1r);
            }
        }
        #pragma unroll
        for (int mt = 0; mt < 4; mt++) {
            int r0 = wm*64 + mt*16 + qr;
            int c0 = wn*32 + half*8 + qt*2;
            float t0 = tBs[c0], t1 = tBs[c0+1];
            float s0 = sAs[r0], s1 = sAs[r0+8];
            Cs[r0*132 + c0]       = (float)(c11[mt][0]*128 + cm[mt][0]) * s0 * t0;
            Cs[r0*132 + c0 + 1]   = (float)(c11[mt][1]*128 + cm[mt][1]) * s0 * t1;
            Cs[(r0+8)*132 + c0]   = (float)(c11[mt][2]*128 + cm[mt][2]) * s1 * t0;
            Cs[(r0+8)*132 + c0+1] = (float)(c11[mt][3]*128 + cm[mt][3]) * s1 * t1;
        }
    }
    __syncthreads();
    for (int o = tid; o < 1984; o += 256) {     // 8b x 8co x 31t
        int t = o % 31, tmp = o / 31;
        int co_l = tmp & 7, bl2 = tmp >> 3;
        int lo = (t > 15) ? (t - 15) : 0;
        int hi = (t < 15) ? t : 15;
        float s = 0.f;
        for (int tp = lo; tp <= hi; tp++)
            s += Cs[(bl2*16 + tp)*132 + co_l*16 + (t - tp)];
        g_y2[br][((my*8 + bl2)*256 + nx*8 + co_l)*31 + t] = s;
    }
}

// ---------------- kernel: BN stats conv2 ----------------
__global__ __launch_bounds__(256) void k_bnstats2(
    const float* __restrict__ hg, const float* __restrict__ hb,
    const float* __restrict__ wg, const float* __restrict__ wb)
{
    const int co = blockIdx.x, br = blockIdx.y, b = threadIdx.x;
    const float* p = g_y2[br] + (b*256 + co)*31;
    float s = 0.f, q = 0.f;
    #pragma unroll
    for (int t = 0; t < 31; t++) { float v = p[t]; s += v; q += v*v; }
    wreduce2(s, q);
    __shared__ float sp[8], qp[8];
    if ((b & 31) == 0) { sp[b >> 5] = s; qp[b >> 5] = q; }
    __syncthreads();
    if (b == 0) {
        float ts = 0.f, tq = 0.f;
        #pragma unroll
        for (int i = 0; i < 8; i++) { ts += sp[i]; tq += qp[i]; }
        const float inv = 1.f/(256.f*31.f);
        float m   = ts*inv;
        float var = tq*inv - m*m;
        float gam = br ? wg[co] : hg[co];
        float bet = br ? wb[co] : hb[co];
        float a   = gam*rsqrtf(var + 1e-5f);
        g_ab2[br][0][co] = a;
        g_ab2[br][1][co] = bet - m*a;
    }
}

// ---------------- prepA3: BN+lrelu, row amax, quantize to fragment order ----------
__global__ __launch_bounds__(256) void k_prepA3q()
{
    const int b = blockIdx.x, br = blockIdx.y, tid = threadIdx.x;
    const int lane = tid & 31, wrp = tid >> 5;
    __shared__ float ys[256*33];
    __shared__ float aAs[256], aSs[256];
    __shared__ float invs[32];
    aAs[tid] = g_ab2[br][0][tid];
    aSs[tid] = g_ab2[br][1][tid];
    __syncthreads();
    for (int idx = tid; idx < 7936; idx += 256) {
        int ci = idx / 31, t = idx % 31;
        float v = g_y2[br][b*7936 + idx];
        v = fmaf(aAs[ci], v, aSs[ci]);
        v = (v >= 0.f) ? v : 0.2f*v;
        ys[ci*33 + t] = v;
    }
    __syncthreads();
    #pragma unroll
    for (int rr = 0; rr < 4; rr++) {
        int tp = wrp*4 + rr;
        float m = 0.f;
        if (tp < 31) {
            #pragma unroll
            for (int c8 = 0; c8 < 8; c8++) m = fmaxf(m, fabsf(ys[(lane + c8*32)*33 + tp]));
        }
        #pragma unroll
        for (int o = 16; o > 0; o >>= 1) m = fmaxf(m, __shfl_xor_sync(0xffffffffu, m, o));
        if (lane == 0) {
            g_sA3[br][b*32 + tp] = m * (1.f/16256.f);
            invs[tp] = (m > 0.f) ? 16256.f/m : 0.f;
        }
    }
    __syncthreads();
    #pragma unroll
    for (int it = 0; it < 8; it++) {
        int widx = tid + it*256;        // 0..2047
        int mih = widx >> 10, rem = widx & 1023;
        int ks = rem >> 7, rem2 = rem & 127;
        int ln = rem2 >> 2, w = rem2 & 3;
        int qr = ln >> 2, qt = ln & 3;
        int r = ((w & 1) << 3) | qr;
        int tp = (mih << 4) | r;
        int kb = ((w >> 1) << 4) | (qt << 2);
        u32 p1 = 0, p0 = 0;
        if (tp < 31) {
            float inv = invs[tp];
            #pragma unroll
            for (int j = 0; j < 4; j++) {
                int ci = ks*32 + kb + j;
                QUANT_PACK(ys[ci*33 + tp], inv, p1, p0, j);
            }
        }
        int addr = (((b*2 + mih)*8 + ks)*32 + ln)*4 + w;
        g_A3q1[br][addr] = p1;
        g_A3q0[br][addr] = p0;
    }
}

// ---------------- conv3: int8 dual-digit mma.sync, fold + bias + tanh ------
__global__ __launch_bounds__(256, 2) void k_conv3q(
    const float* __restrict__ bh3, const float* __restrict__ bw3)
{
    const int br = blockIdx.z, nx = blockIdx.x, my = blockIdx.y;
    const float* __restrict__ bias = br ? bw3 : bh3;
    const int tid = threadIdx.x, lane = tid & 31, wid = tid >> 5;
    const int wm = wid >> 2, wn = wid & 3;
    const int qr = lane >> 2, qt = lane & 3;
    __shared__ float sAs[128], tBs[128];
    if (tid < 128) sAs[tid] = g_sA3[br][my*128 + tid] * 128.f;
    else           tBs[tid-128] = g_tB3[br][nx*128 + (tid-128)];
    const u32* __restrict__ A1 = g_A3q1[br];
    const u32* __restrict__ A0 = g_A3q0[br];
    const u32* __restrict__ B1 = g_B3q1[br];
    const u32* __restrict__ B0 = g_B3q0[br];
    const int mi0 = my*8 + wm*4;
    float* Cs = (float*)smw;                    // 128 x 132
    __syncthreads();
    #pragma unroll
    for (int half = 0; half < 4; half++) {
        const int ni = nx*16 + wn*4 + half;
        int c11[4][4] = {}, cm[4][4] = {};
        #pragma unroll
        for (int ks = 0; ks < 8; ks++) {
            int ba = ((ni*8 + ks)*32 + lane)*2;
            uint2 b1v = *(const uint2*)(B1 + ba);
            uint2 b0v = *(const uint2*)(B0 + ba);
            u32 b1r[2] = {b1v.x, b1v.y};
            u32 b0r[2] = {b0v.x, b0v.y};
            #pragma unroll
            for (int mt = 0; mt < 4; mt++) {
                int aa = (((mi0+mt)*8 + ks)*32 + lane)*4;
                uint4 a1v = *(const uint4*)(A1 + aa);
                uint4 a0v = *(const uint4*)(A0 + aa);
                u32 a1r[4] = {a1v.x, a1v.y, a1v.z, a1v.w};
                u32 a0r[4] = {a0v.x, a0v.y, a0v.z, a0v.w};
                MMAS8(c11[mt], a1r, b1r);
                MMAS8(cm[mt],  a1r, b0r);
                MMAS8(cm[mt],  a0r, b1r);
            }
        }
        #pragma unroll
        for (int mt = 0; mt < 4; mt++) {
            int r0 = wm*64 + mt*16 + qr;
            int c0 = wn*32 + half*8 + qt*2;
            float t0 = tBs[c0], t1 = tBs[c0+1];
            float s0 = sAs[r0], s1 = sAs[r0+8];
            Cs[r0*132 + c0]       = (float)(c11[mt][0]*128 + cm[mt][0]) * s0 * t0;
            Cs[r0*132 + c0 + 1]   = (float)(c11[mt][1]*128 + cm[mt][1]) * s0 * t1;
            Cs[(r0+8)*132 + c0]   = (float)(c11[mt][2]*128 + cm[mt][2]) * s1 * t0;
            Cs[(r0+8)*132 + c0+1] = (float)(c11[mt][3]*128 + cm[mt][3]) * s1 * t1;
        }
    }
    __syncthreads();
    for (int i = 0; i < 32; i++) {
        int idx = tid + i*256;                  // 8192 outputs
        int t = idx & 31, co_l = (idx >> 5) & 63, bl2 = idx >> 11;
        int row = bl2*32 + t;
        float v = Cs[row*132 + 2*co_l];
        if (t > 0) v += Cs[(row-1)*132 + 2*co_l + 1];
        v += bias[nx*64 + co_l];
        g_hw[br][((my*4 + bl2)*512 + nx*64 + co_l)*32 + t] = tanhf(v);
    }
}

// ---------------- kernel: final einsum ----------------
__global__ __launch_bounds__(256) void k_final(const float* __restrict__ coef,
                                               float* __restrict__ out)
{
    const int b = blockIdx.x, tid = threadIdx.x;
    __shared__ __align__(16) float4 cs[128];
    __shared__ __align__(16) float  hs [128*32];
    __shared__ __align__(16) float  ws2[128*32];
    const int p0 = tid*4, hh = p0 >> 5, ww0 = p0 & 31;
    float acc[4][3];
    #pragma unroll
    for (int i = 0; i < 4; i++)
        #pragma unroll
        for (int c = 0; c < 3; c++) acc[i][c] = 0.f;
    for (int chk = 0; chk < 4; chk++) {
        const int r0 = chk*128;
        __syncthreads();
        if (tid < 128) {
            const int r = r0 + tid;
            const float* cp = g_craw + b*1536 + r*3;
            float a = g_abc[0][r], sh = g_abc[1][r];
            float cf = coef[r];
            float v0 = fmaf(a, cp[0], sh); v0 = (v0 >= 0.f) ? v0 : 0.2f*v0;
            float v1 = fmaf(a, cp[1], sh); v1 = (v1 >= 0.f) ? v1 : 0.2f*v1;
            float v2 = fmaf(a, cp[2], sh); v2 = (v2 >= 0.f) ? v2 : 0.2f*v2;
            cs[tid] = make_float4(v0*cf, v1*cf, v2*cf, 0.f);
        }
        for (int idx = tid; idx < 4096; idx += 256) {
            hs [idx] = g_hw[0][(b*512 + r0)*32 + idx];
            ws2[idx] = g_hw[1][(b*512 + r0)*32 + idx];
        }
        __syncthreads();
        for (int r = 0; r < 128; r++) {
            float4 c4 = cs[r];
            float  hv = hs[r*32 + hh];
            float4 wv = *reinterpret_cast<const float4*>(&ws2[r*32 + ww0]);
            float p;
            p = hv*wv.x; acc[0][0] += p*c4.x; acc[0][1] += p*c4.y; acc[0][2] += p*c4.z;
            p = hv*wv.y; acc[1][0] += p*c4.x; acc[1][1] += p*c4.y; acc[1][2] += p*c4.z;
            p = hv*wv.z; acc[2][0] += p*c4.x; acc[2][1] += p*c4.y; acc[2][2] += p*c4.z;
            p = hv*wv.w; acc[3][0] += p*c4.x; acc[3][1] += p*c4.y; acc[3][2] += p*c4.z;
        }
    }
    #pragma unroll
    for (int c = 0; c < 3; c++)
        #pragma unroll
        for (int i = 0; i < 4; i++)
            out[((b*3 + c)*32 + hh)*32 + ww0 + i] = acc[i][c];
}

// ---------------- launch ----------------
extern "C" void kernel_launch(void* const* d_in, const int* in_sizes, int n_in,
                              void* d_out, int out_size)
{
    const float* noise = (const float*)d_in[0];
    const int*   label = (const int*)  d_in[1];
    const float* lin_w = (const float*)d_in[2];
    const float* bn0_g = (const float*)d_in[4];
    const float* bn0_b = (const float*)d_in[5];
    const float* emb   = (const float*)d_in[6];
    const float* c_w1  = (const float*)d_in[7];
    const float* c_g1  = (const float*)d_in[9];
    const float* c_be1 = (const float*)d_in[10];
    const float* h_w1  = (const float*)d_in[11];
    const float* h_g1  = (const float*)d_in[13];
    const float* h_be1 = (const float*)d_in[14];
    const float* h_w2  = (const float*)d_in[15];
    const float* h_g2  = (const float*)d_in[17];
    const float* h_be2 = (const float*)d_in[18];
    const float* h_w3  = (const float*)d_in[19];
    const float* h_b3  = (const float*)d_in[20];
    const float* w_w1  = (const float*)d_in[21];
    const float* w_g1  = (const float*)d_in[23];
    const float* w_be1 = (const float*)d_in[24];
    const float* w_w2  = (const float*)d_in[25];
    const float* w_g2  = (const float*)d_in[27];
    const float* w_be2 = (const float*)d_in[28];
    const float* w_w3  = (const float*)d_in[29];
    const float* w_b3  = (const float*)d_in[30];
    const float* coef  = (const float*)d_in[31];
    float* out = (float*)d_out;

    const int SMEM_C  = 128*132*4;   // 67584 B conv epilogue buffer
    const int SMEM_W  = 256*65*4;    // 66560 B weight-prep tile
    cudaFuncSetAttribute(k_conv2q, cudaFuncAttributeMaxDynamicSharedMemorySize, SMEM_C);
    cudaFuncSetAttribute(k_conv3q, cudaFuncAttributeMaxDynamicSharedMemorySize, SMEM_C);
    cudaFuncSetAttribute(k_combo,  cudaFuncAttributeMaxDynamicSharedMemorySize, SMEM_W);

    k_combo<<<416, 256, SMEM_W>>>(noise, label, lin_w, bn0_g, bn0_b, emb,
                                  h_w2, w_w2, h_w3, w_w3);

    k_gemm1m<<<dim3(32, 4, 3), 256>>>(c_w1, h_w1, w_w1);

    k_bnstats1<<<768, 256>>>(c_g1, c_be1, h_g1, h_be1, w_g1, w_be1);

    k_prepA2q<<<dim3(256, 2), 256>>>();

    k_conv2q<<<dim3(32, 32, 2), 256, SMEM_C>>>();

    k_bnstats2<<<dim3(256, 2), 256>>>(h_g2, h_be2, w_g2, w_be2);

    k_prepA3q<<<dim3(256, 2), 256>>>();

    k_conv3q<<<dim3(8, 64, 2), 256, SMEM_C>>>(h_b3, w_b3);

    k_final<<<256, 256>>>(coef, out);
}

// round 13
// speedup vs baseline: 1.5396x; 1.5396x over previous
#include <cuda_runtime.h>
#include <cuda_bf16.h>
#include <math.h>
#include <stdint.h>

typedef uint32_t u32;

// ---------------- scratch (device globals; no allocation) ----------------
__device__ float g_latT [256*256];
__device__ float g_craw [256*1536];
__device__ float g_x1raw[2][256*2048];
__device__ float g_y2   [2][256*256*31];
__device__ float g_abc  [2][512];
__device__ float g_abhw [2][2][128];
__device__ float g_ab2  [2][2][256];
__device__ float g_hw   [2][256*512*32];
// fragment-order bf16 operands: A [mi][ks][lane][4 words], B [ni][ks][lane][2 words]
__device__ __align__(16) u32 g_A2f [2][256*8*32*4];
__device__ __align__(16) u32 g_A2fl[2][256*8*32*4];
__device__ __align__(16) u32 g_B2f [2][512*8*32*2];
__device__ __align__(16) u32 g_B2fl[2][512*8*32*2];
__device__ __align__(16) u32 g_A3f [2][512*16*32*4];
__device__ __align__(16) u32 g_A3fl[2][512*16*32*4];
__device__ __align__(16) u32 g_B3f [2][128*16*32*2];
__device__ __align__(16) u32 g_B3fl[2][128*16*32*2];

__device__ __forceinline__ u32 packbf(float x, float y) {
    __nv_bfloat162 t;
    t.x = __float2bfloat16(x);
    t.y = __float2bfloat16(y);
    return *reinterpret_cast<u32*>(&t);
}
__device__ __forceinline__ void split_pair(float v0, float v1, u32& hw, u32& lw) {
    __nv_bfloat16 h0 = __float2bfloat16(v0), h1 = __float2bfloat16(v1);
    float r0 = v0 - __bfloat162float(h0), r1 = v1 - __bfloat162float(h1);
    __nv_bfloat162 th; th.x = h0; th.y = h1;
    hw = *reinterpret_cast<u32*>(&th);
    lw = packbf(r0, r1);
}
__device__ __forceinline__ void wreduce2(float& s, float& q) {
    #pragma unroll
    for (int o = 16; o > 0; o >>= 1) {
        s += __shfl_xor_sync(0xffffffffu, s, o);
        q += __shfl_xor_sync(0xffffffffu, q, o);
    }
}

#define MMA16816(c, a, b) \
    asm volatile("mma.sync.aligned.m16n8k16.row.col.f32.bf16.bf16.f32 " \
                 "{%0,%1,%2,%3}, {%4,%5,%6,%7}, {%8,%9}, {%0,%1,%2,%3};" \
                 : "+f"((c)[0]), "+f"((c)[1]), "+f"((c)[2]), "+f"((c)[3]) \
                 : "r"((a)[0]), "r"((a)[1]), "r"((a)[2]), "r"((a)[3]), \
                   "r"((b)[0]), "r"((b)[1]))

// ---------------- kernel 1: latent + prepB combo (independent work) ----------------
__global__ __launch_bounds__(256) void k_combo(
    const float* __restrict__ noise, const int* __restrict__ label,
    const float* __restrict__ lin_w, const float* __restrict__ bn0_g,
    const float* __restrict__ bn0_b, const float* __restrict__ emb,
    const float* __restrict__ W2h, const float* __restrict__ W2w,
    const float* __restrict__ W3h, const float* __restrict__ W3w)
{
    const int bid = blockIdx.x, tid = threadIdx.x;
    if (bid < 256) {
        // ---- latent ----
        const int ch = bid, b = tid;
        if (ch >= 128) {
            g_latT[ch*256 + b] = emb[label[b]*128 + (ch - 128)];
            return;
        }
        __shared__ float wsm[100];
        if (b < 100) wsm[b] = lin_w[ch*100 + b];
        __syncthreads();
        const float* nr = noise + b*100;
        float z = 0.f;
        #pragma unroll 4
        for (int i = 0; i < 100; i++) z += nr[i]*wsm[i];
        float s = z, q = z*z;
        wreduce2(s, q);
        __shared__ float sp[8], qp[8];
        if ((b & 31) == 0) { sp[b >> 5] = s; qp[b >> 5] = q; }
        __syncthreads();
        float ts = 0.f, tq = 0.f;
        #pragma unroll
        for (int i = 0; i < 8; i++) { ts += sp[i]; tq += qp[i]; }
        float m   = ts*(1.f/256.f);
        float var = tq*(1.f/256.f) - m*m;
        float a   = bn0_g[ch]*rsqrtf(var + 1e-5f);
        float y   = (z - m)*a + bn0_b[ch];
        g_latT[ch*256 + b] = (y >= 0.f) ? y : 0.01f*y;
        return;
    }
    // ---- prepB: weights -> fragment-order bf16 hi/lo ----
    int gid = (bid - 256)*256 + tid;
    if (gid < 524288) {                       // W2: 2 br x 4096 n x 64 cp
        int br = gid >> 18, n = (gid >> 6) & 4095, cp = gid & 63;
        const float* W = br ? W2w : W2h;      // row-major [ci][4096]
        float v0 = W[(2*cp)*4096 + n];
        float v1 = W[(2*cp + 1)*4096 + n];
        u32 hw, lw; split_pair(v0, v1, hw, lw);
        int ni = n >> 3, ks = cp >> 3, cpl = cp & 7;
        int lane = (n & 7)*4 + (cpl & 3), w = cpl >> 2;
        int addr = ((ni*8 + ks)*32 + lane)*2 + w;
        g_B2f [br][addr] = hw;
        g_B2fl[br][addr] = lw;
    } else {                                  // W3: 2 br x 1024 n x 128 cp
        int g2 = gid - 524288;
        int br = g2 >> 17, n = (g2 >> 7) & 1023, cp = g2 & 127;
        const float* W = br ? W3w : W3h;      // [ci][1024]
        float v0 = W[(2*cp)*1024 + n];
        float v1 = W[(2*cp + 1)*1024 + n];
        u32 hw, lw; split_pair(v0, v1, hw, lw);
        int ni = n >> 3, ks = cp >> 3, cpl = cp & 7;
        int lane = (n & 7)*4 + (cpl & 3), w = cpl >> 2;
        int addr = ((ni*16 + ks)*32 + lane)*2 + w;
        g_B3f [br][addr] = hw;
        g_B3fl[br][addr] = lw;
    }
}

// ---------------- kernel 2: conv1 GEMMs, all branches (raw) ----------------
__global__ __launch_bounds__(256) void k_gemm1m(
    const float* __restrict__ Wc, const float* __restrict__ Wh,
    const float* __restrict__ Ww)
{
    const int z = blockIdx.z;
    int N; const float* W; float* O;
    if (z == 2) {
        if (blockIdx.x >= 24) return;
        N = 1536; W = Wc; O = g_craw;
    } else {
        N = 2048; W = z ? Ww : Wh; O = g_x1raw[z];
    }
    const int n0 = blockIdx.x*64, b0 = blockIdx.y*64;
    const int tid = threadIdx.x, tx = tid & 15, ty = tid >> 4;
    __shared__ float Xs[16][68], Ws[16][68];
    float acc[4][4] = {};
    for (int k0 = 0; k0 < 256; k0 += 16) {
        __syncthreads();
        for (int i = tid; i < 1024; i += 256) {
            int k = i >> 6, c = i & 63;
            Xs[k][c] = g_latT[(k0+k)*256 + b0 + c];
            Ws[k][c] = W[(k0+k)*N + n0 + c];
        }
        __syncthreads();
        #pragma unroll
        for (int k = 0; k < 16; k++) {
            float4 x4 = *(const float4*)&Xs[k][ty*4];
            float4 w4 = *(const float4*)&Ws[k][tx*4];
            float xa[4] = {x4.x, x4.y, x4.z, x4.w};
            float wa[4] = {w4.x, w4.y, w4.z, w4.w};
            #pragma unroll
            for (int i = 0; i < 4; i++)
                #pragma unroll
                for (int j = 0; j < 4; j++) acc[i][j] += xa[i]*wa[j];
        }
    }
    #pragma unroll
    for (int i = 0; i < 4; i++) {
        float4 v = make_float4(acc[i][0], acc[i][1], acc[i][2], acc[i][3]);
        *(float4*)&O[(b0 + ty*4 + i)*N + n0 + tx*4] = v;
    }
}

// ---------------- kernel 3: BN stats conv1 ----------------
__global__ __launch_bounds__(256) void k_bnstats1(
    const float* __restrict__ cg, const float* __restrict__ cb,
    const float* __restrict__ hg, const float* __restrict__ hb,
    const float* __restrict__ wg, const float* __restrict__ wb)
{
    const int bid = blockIdx.x, b = threadIdx.x;
    float s = 0.f, q = 0.f; float invn; float gam, bet;
    int which, br = 0, co;
    if (bid < 512) {
        which = 0; co = bid;
        const float* p = g_craw + b*1536 + co*3;
        #pragma unroll
        for (int l = 0; l < 3; l++) { float v = p[l]; s += v; q += v*v; }
        invn = 1.f/(256.f*3.f); gam = cg[co]; bet = cb[co];
    } else {
        which = 1; int idx = bid - 512; br = idx >> 7; co = idx & 127;
        const float* p = g_x1raw[br] + b*2048 + co*16;
        #pragma unroll
        for (int l = 0; l < 16; l++) { float v = p[l]; s += v; q += v*v; }
        invn = 1.f/(256.f*16.f);
        gam = br ? wg[co] : hg[co]; bet = br ? wb[co] : hb[co];
    }
    wreduce2(s, q);
    __shared__ float sp[8], qp[8];
    if ((b & 31) == 0) { sp[b >> 5] = s; qp[b >> 5] = q; }
    __syncthreads();
    if (b == 0) {
        float ts = 0.f, tq = 0.f;
        #pragma unroll
        for (int i = 0; i < 8; i++) { ts += sp[i]; tq += qp[i]; }
        float m   = ts*invn;
        float var = tq*invn - m*m;
        float a   = gam*rsqrtf(var + 1e-5f);
        float sh  = bet - m*a;
        if (which == 0) { g_abc[0][co] = a; g_abc[1][co] = sh; }
        else            { g_abhw[br][0][co] = a; g_abhw[br][1][co] = sh; }
    }
}

// ---------------- prepA2: per-batch smem tile, coalesced both ways ----------------
// block (b, br): load x1raw row (2048 floats), BN+lrelu+split -> fragment uint4s.
__global__ __launch_bounds__(256) void k_prepA2n()
{
    const int b = blockIdx.x, br = blockIdx.y, tid = threadIdx.x;
    __shared__ float xs[128*17];     // [ci*17 + l], padded
    __shared__ float aAs[128], aSs[128];
    for (int idx = tid; idx < 2048; idx += 256) {
        float v = g_x1raw[br][b*2048 + idx];
        xs[(idx >> 4)*17 + (idx & 15)] = v;
    }
    if (tid < 128) {
        aAs[tid] = g_abhw[br][0][tid];
        aSs[tid] = g_abhw[br][1][tid];
    }
    __syncthreads();
    const int ks = tid >> 5, lane = tid & 31;
    u32 oh[4], ol[4];
    #pragma unroll
    for (int w = 0; w < 4; w++) {
        int cpl2 = w >> 1, l3 = w & 1;
        int l   = (l3 << 3) | (lane >> 2);
        int cpl = (cpl2 << 2) | (lane & 3);
        int ci  = (ks*8 + cpl)*2;
        float v0 = fmaf(aAs[ci],   xs[ci*17 + l],     aSs[ci]);
        float v1 = fmaf(aAs[ci+1], xs[(ci+1)*17 + l], aSs[ci+1]);
        v0 = (v0 >= 0.f) ? v0 : 0.2f*v0;
        v1 = (v1 >= 0.f) ? v1 : 0.2f*v1;
        split_pair(v0, v1, oh[w], ol[w]);
    }
    int addr = ((b*8 + ks)*32 + lane)*4;
    *(uint4*)&g_A2f [br][addr] = make_uint4(oh[0], oh[1], oh[2], oh[3]);
    *(uint4*)&g_A2fl[br][addr] = make_uint4(ol[0], ol[1], ol[2], ol[3]);
}

// ---------------- conv2: fragment-direct mma.sync ----------------
extern __shared__ u32 smw[];
__global__ __launch_bounds__(256, 2) void k_conv2f()
{
    const int br = blockIdx.z, nx = blockIdx.x, my = blockIdx.y;
    const int tid = threadIdx.x, lane = tid & 31, wid = tid >> 5;
    const int wm = wid >> 2, wn = wid & 3;
    const u32* __restrict__ AH = g_A2f [br];
    const u32* __restrict__ AL = g_A2fl[br];
    const u32* __restrict__ BH = g_B2f [br];
    const u32* __restrict__ BL = g_B2fl[br];
    const int mi0 = my*8 + wm*4;
    const int ni0 = nx*16 + wn*4;
    float acc[4][4][4] = {};
    #pragma unroll
    for (int ks = 0; ks < 8; ks++) {
        u32 bh[4][2], bl[4][2];
        #pragma unroll
        for (int nt = 0; nt < 4; nt++) {
            int ba = (((ni0+nt)*8 + ks)*32 + lane)*2;
            uint2 vh = *(const uint2*)(BH + ba); bh[nt][0] = vh.x; bh[nt][1] = vh.y;
            uint2 vl = *(const uint2*)(BL + ba); bl[nt][0] = vl.x; bl[nt][1] = vl.y;
        }
        #pragma unroll
        for (int mt = 0; mt < 4; mt++) {
            int aa = (((mi0+mt)*8 + ks)*32 + lane)*4;
            uint4 vh = *(const uint4*)(AH + aa);
            uint4 vl = *(const uint4*)(AL + aa);
            u32 ah[4] = {vh.x, vh.y, vh.z, vh.w};
            u32 al[4] = {vl.x, vl.y, vl.z, vl.w};
            #pragma unroll
            for (int nt = 0; nt < 4; nt++) {
                MMA16816(acc[mt][nt], ah, bh[nt]);
                MMA16816(acc[mt][nt], ah, bl[nt]);
                MMA16816(acc[mt][nt], al, bh[nt]);
            }
        }
    }
    float* Cs = (float*)smw;                    // 128 x 132
    const int qr = lane >> 2, qt = lane & 3;
    #pragma unroll
    for (int mt = 0; mt < 4; mt++)
        #pragma unroll
        for (int nt = 0; nt < 4; nt++) {
            int r0 = wm*64 + mt*16 + qr, c0 = wn*32 + nt*8 + qt*2;
            Cs[r0*132 + c0]       = acc[mt][nt][0];
            Cs[r0*132 + c0 + 1]   = acc[mt][nt][1];
            Cs[(r0+8)*132 + c0]   = acc[mt][nt][2];
            Cs[(r0+8)*132 + c0+1] = acc[mt][nt][3];
        }
    __syncthreads();
    for (int o = tid; o < 1984; o += 256) {     // 8b x 8co x 31t
        int t = o % 31, tmp = o / 31;
        int co_l = tmp & 7, bl2 = tmp >> 3;
        int lo = (t > 15) ? (t - 15) : 0;
        int hi = (t < 15) ? t : 15;
        float s = 0.f;
        for (int tp = lo; tp <= hi; tp++)
            s += Cs[(bl2*16 + tp)*132 + co_l*16 + (t - tp)];
        g_y2[br][((my*8 + bl2)*256 + nx*8 + co_l)*31 + t] = s;
    }
}

// ---------------- kernel: BN stats conv2 ----------------
__global__ __launch_bounds__(256) void k_bnstats2(
    const float* __restrict__ hg, const float* __restrict__ hb,
    const float* __restrict__ wg, const float* __restrict__ wb)
{
    const int co = blockIdx.x, br = blockIdx.y, b = threadIdx.x;
    const float* p = g_y2[br] + (b*256 + co)*31;
    float s = 0.f, q = 0.f;
    #pragma unroll
    for (int t = 0; t < 31; t++) { float v = p[t]; s += v; q += v*v; }
    wreduce2(s, q);
    __shared__ float sp[8], qp[8];
    if ((b & 31) == 0) { sp[b >> 5] = s; qp[b >> 5] = q; }
    __syncthreads();
    if (b == 0) {
        float ts = 0.f, tq = 0.f;
        #pragma unroll
        for (int i = 0; i < 8; i++) { ts += sp[i]; tq += qp[i]; }
        const float inv = 1.f/(256.f*31.f);
        float m   = ts*inv;
        float var = tq*inv - m*m;
        float gam = br ? wg[co] : hg[co];
        float bet = br ? wb[co] : hb[co];
        float a   = gam*rsqrtf(var + 1e-5f);
        g_ab2[br][0][co] = a;
        g_ab2[br][1][co] = bet - m*a;
    }
}

// ---------------- prepA3: per-batch smem tile, coalesced both ways ----------------
// block (b, br): load y2 row (7936 floats), BN+lrelu+split -> fragment uint4s.
__global__ __launch_bounds__(256) void k_prepA3n()
{
    const int b = blockIdx.x, br = blockIdx.y, tid = threadIdx.x;
    __shared__ float ys[256*33];     // [ci*33 + t], padded
    __shared__ float aAs[256], aSs[256];
    for (int idx = tid; idx < 7936; idx += 256) {
        float v = g_y2[br][b*7936 + idx];
        ys[(idx / 31)*33 + (idx % 31)] = v;
    }
    if (tid < 256) {
        aAs[tid] = g_ab2[br][0][tid];
        aSs[tid] = g_ab2[br][1][tid];
    }
    __syncthreads();
    const int lane = tid & 31;
    #pragma unroll
    for (int it = 0; it < 2; it++) {
        const int ks = (tid >> 5) + 8*it;
        #pragma unroll
        for (int mih = 0; mih < 2; mih++) {
            u32 oh[4], ol[4];
            #pragma unroll
            for (int w = 0; w < 4; w++) {
                int cpl2 = w >> 1, r3 = w & 1;
                int r   = (r3 << 3) | (lane >> 2);
                int tp  = (mih << 4) | r;
                int cpl = (cpl2 << 2) | (lane & 3);
                int ci  = (ks*8 + cpl)*2;
                float v0 = 0.f, v1 = 0.f;
                if (tp < 31) {
                    v0 = fmaf(aAs[ci],   ys[ci*33 + tp],     aSs[ci]);
                    v1 = fmaf(aAs[ci+1], ys[(ci+1)*33 + tp], aSs[ci+1]);
                    v0 = (v0 >= 0.f) ? v0 : 0.2f*v0;
                    v1 = (v1 >= 0.f) ? v1 : 0.2f*v1;
                }
                split_pair(v0, v1, oh[w], ol[w]);
            }
            int mi = b*2 + mih;
            int addr = ((mi*16 + ks)*32 + lane)*4;
            *(uint4*)&g_A3f [br][addr] = make_uint4(oh[0], oh[1], oh[2], oh[3]);
            *(uint4*)&g_A3fl[br][addr] = make_uint4(ol[0], ol[1], ol[2], ol[3]);
        }
    }
}

// ---------------- conv3: fragment-direct mma.sync, fold + bias + tanh ------
__global__ __launch_bounds__(256, 2) void k_conv3f(
    const float* __restrict__ bh3, const float* __restrict__ bw3)
{
    const int br = blockIdx.z, nx = blockIdx.x, my = blockIdx.y;
    const float* __restrict__ bias = br ? bw3 : bh3;
    const int tid = threadIdx.x, lane = tid & 31, wid = tid >> 5;
    const int wm = wid >> 2, wn = wid & 3;
    const u32* __restrict__ AH = g_A3f [br];
    const u32* __restrict__ AL = g_A3fl[br];
    const u32* __restrict__ BH = g_B3f [br];
    const u32* __restrict__ BL = g_B3fl[br];
    const int mi0 = my*8 + wm*4;
    const int ni0 = nx*16 + wn*4;
    float acc[4][4][4] = {};
    #pragma unroll
    for (int ks = 0; ks < 16; ks++) {
        u32 bh[4][2], bl[4][2];
        #pragma unroll
        for (int nt = 0; nt < 4; nt++) {
            int ba = (((ni0+nt)*16 + ks)*32 + lane)*2;
            uint2 vh = *(const uint2*)(BH + ba); bh[nt][0] = vh.x; bh[nt][1] = vh.y;
            uint2 vl = *(const uint2*)(BL + ba); bl[nt][0] = vl.x; bl[nt][1] = vl.y;
        }
        #pragma unroll
        for (int mt = 0; mt < 4; mt++) {
            int aa = (((mi0+mt)*16 + ks)*32 + lane)*4;
            uint4 vh = *(const uint4*)(AH + aa);
            uint4 vl = *(const uint4*)(AL + aa);
            u32 ah[4] = {vh.x, vh.y, vh.z, vh.w};
            u32 al[4] = {vl.x, vl.y, vl.z, vl.w};
            #pragma unroll
            for (int nt = 0; nt < 4; nt++) {
                MMA16816(acc[mt][nt], ah, bh[nt]);
                MMA16816(acc[mt][nt], ah, bl[nt]);
                MMA16816(acc[mt][nt], al, bh[nt]);
            }
        }
    }
    float* Cs = (float*)smw;                    // 128 x 132
    const int qr = lane >> 2, qt = lane & 3;
    #pragma unroll
    for (int mt = 0; mt < 4; mt++)
        #pragma unroll
        for (int nt = 0; nt < 4; nt++) {
            int r0 = wm*64 + mt*16 + qr, c0 = wn*32 + nt*8 + qt*2;
            Cs[r0*132 + c0]       = acc[mt][nt][0];
            Cs[r0*132 + c0 + 1]   = acc[mt][nt][1];
            Cs[(r0+8)*132 + c0]   = acc[mt][nt][2];
            Cs[(r0+8)*132 + c0+1] = acc[mt][nt][3];
        }
    __syncthreads();
    // rows: bl*32 + t' (4 b per CTA), cols: co_l*2 + k (64 co per CTA)
    for (int i = 0; i < 32; i++) {
        int idx = tid + i*256;                  // 8192 outputs
        int t = idx & 31, co_l = (idx >> 5) & 63, bl2 = idx >> 11;
        int row = bl2*32 + t;
        float v = Cs[row*132 + 2*co_l];
        if (t > 0) v += Cs[(row-1)*132 + 2*co_l + 1];
        v += bias[nx*64 + co_l];
        g_hw[br][((my*4 + bl2)*512 + nx*64 + co_l)*32 + t] = tanhf(v);
    }
}

// ---------------- kernel: final einsum ----------------
__global__ __launch_bounds__(256) void k_final(const float* __restrict__ coef,
                                               float* __restrict__ out)
{
    const int b = blockIdx.x, tid = threadIdx.x;
    __shared__ __align__(16) float4 cs[128];
    __shared__ __align__(16) float  hs [128*32];
    __shared__ __align__(16) float  ws2[128*32];
    const int p0 = tid*4, hh = p0 >> 5, ww0 = p0 & 31;
    float acc[4][3];
    #pragma unroll
    for (int i = 0; i < 4; i++)
        #pragma unroll
        for (int c = 0; c < 3; c++) acc[i][c] = 0.f;
    for (int chk = 0; chk < 4; chk++) {
        const int r0 = chk*128;
        __syncthreads();
        if (tid < 128) {
            const int r = r0 + tid;
            const float* cp = g_craw + b*1536 + r*3;
            float a = g_abc[0][r], sh = g_abc[1][r];
            float cf = coef[r];
            float v0 = fmaf(a, cp[0], sh); v0 = (v0 >= 0.f) ? v0 : 0.2f*v0;
            float v1 = fmaf(a, cp[1], sh); v1 = (v1 >= 0.f) ? v1 : 0.2f*v1;
            float v2 = fmaf(a, cp[2], sh); v2 = (v2 >= 0.f) ? v2 : 0.2f*v2;
            cs[tid] = make_float4(v0*cf, v1*cf, v2*cf, 0.f);
        }
        for (int idx = tid; idx < 4096; idx += 256) {
            hs [idx] = g_hw[0][(b*512 + r0)*32 + idx];
            ws2[idx] = g_hw[1][(b*512 + r0)*32 + idx];
        }
        __syncthreads();
        for (int r = 0; r < 128; r++) {
            float4 c4 = cs[r];
            float  hv = hs[r*32 + hh];
            float4 wv = *reinterpret_cast<const float4*>(&ws2[r*32 + ww0]);
            float p;
            p = hv*wv.x; acc[0][0] += p*c4.x; acc[0][1] += p*c4.y; acc[0][2] += p*c4.z;
            p = hv*wv.y; acc[1][0] += p*c4.x; acc[1][1] += p*c4.y; acc[1][2] += p*c4.z;
            p = hv*wv.z; acc[2][0] += p*c4.x; acc[2][1] += p*c4.y; acc[2][2] += p*c4.z;
            p = hv*wv.w; acc[3][0] += p*c4.x; acc[3][1] += p*c4.y; acc[3][2] += p*c4.z;
        }
    }
    #pragma unroll
    for (int c = 0; c < 3; c++)
        #pragma unroll
        for (int i = 0; i < 4; i++)
            out[((b*3 + c)*32 + hh)*32 + ww0 + i] = acc[i][c];
}

// ---------------- launch ----------------
extern "C" void kernel_launch(void* const* d_in, const int* in_sizes, int n_in,
                              void* d_out, int out_size)
{
    const float* noise = (const float*)d_in[0];
    const int*   label = (const int*)  d_in[1];
    const float* lin_w = (const float*)d_in[2];
    const float* bn0_g = (const float*)d_in[4];
    const float* bn0_b = (const float*)d_in[5];
    const float* emb   = (const float*)d_in[6];
    const float* c_w1  = (const float*)d_in[7];
    const float* c_g1  = (const float*)d_in[9];
    const float* c_be1 = (const float*)d_in[10];
    const float* h_w1  = (const float*)d_in[11];
    const float* h_g1  = (const float*)d_in[13];
    const float* h_be1 = (const float*)d_in[14];
    const float* h_w2  = (const float*)d_in[15];
    const float* h_g2  = (const float*)d_in[17];
    const float* h_be2 = (const float*)d_in[18];
    const float* h_w3  = (const float*)d_in[19];
    const float* h_b3  = (const float*)d_in[20];
    const float* w_w1  = (const float*)d_in[21];
    const float* w_g1  = (const float*)d_in[23];
    const float* w_be1 = (const float*)d_in[24];
    const float* w_w2  = (const float*)d_in[25];
    const float* w_g2  = (const float*)d_in[27];
    const float* w_be2 = (const float*)d_in[28];
    const float* w_w3  = (const float*)d_in[29];
    const float* w_b3  = (const float*)d_in[30];
    const float* coef  = (const float*)d_in[31];
    float* out = (float*)d_out;

    const int SMEM = 128*132*4;  // 67584 B (epilogue C buffer)
    cudaFuncSetAttribute(k_conv2f, cudaFuncAttributeMaxDynamicSharedMemorySize, SMEM);
    cudaFuncSetAttribute(k_conv3f, cudaFuncAttributeMaxDynamicSharedMemorySize, SMEM);

    k_combo<<<3328, 256>>>(noise, label, lin_w, bn0_g, bn0_b, emb,
                           h_w2, w_w2, h_w3, w_w3);

    k_gemm1m<<<dim3(32, 4, 3), 256>>>(c_w1, h_w1, w_w1);

    k_bnstats1<<<768, 256>>>(c_g1, c_be1, h_g1, h_be1, w_g1, w_be1);

    k_prepA2n<<<dim3(256, 2), 256>>>();

    k_conv2f<<<dim3(32, 32, 2), 256, SMEM>>>();

    k_bnstats2<<<dim3(256, 2), 256>>>(h_g2, h_be2, w_g2, w_be2);

    k_prepA3n<<<dim3(256, 2), 256>>>();

    k_conv3f<<<dim3(8, 64, 2), 256, SMEM>>>(h_b3, w_b3);

    k_final<<<256, 256>>>(coef, out);
}

// round 14
// speedup vs baseline: 1.6290x; 1.0581x over previous
#include <cuda_runtime.h>
#include <cuda_bf16.h>
#include <math.h>
#include <stdint.h>

typedef uint32_t u32;

// ---------------- scratch (device globals; no allocation) ----------------
__device__ float g_latT [256*256];
__device__ float g_craw [256*1536];
__device__ float g_x1raw[2][256*2048];
__device__ float g_y2   [2][256*256*31];
__device__ float g_abc  [2][512];
__device__ float g_abhw [2][2][128];
__device__ float g_st2  [2][2][256];        // conv2 BN stat accumulators (sum, sumsq)
__device__ float g_hw   [2][256*512*32];
// fragment-order bf16 operands: A [mi][ks][lane][4 words], B [ni][ks][lane][2 words]
__device__ __align__(16) u32 g_A2f [2][256*8*32*4];
__device__ __align__(16) u32 g_A2fl[2][256*8*32*4];
__device__ __align__(16) u32 g_B2f [2][512*8*32*2];
__device__ __align__(16) u32 g_B2fl[2][512*8*32*2];
__device__ __align__(16) u32 g_A3f [2][512*16*32*4];
__device__ __align__(16) u32 g_A3fl[2][512*16*32*4];
__device__ __align__(16) u32 g_B3f [2][128*16*32*2];
__device__ __align__(16) u32 g_B3fl[2][128*16*32*2];

__device__ __forceinline__ u32 packbf(float x, float y) {
    __nv_bfloat162 t;
    t.x = __float2bfloat16(x);
    t.y = __float2bfloat16(y);
    return *reinterpret_cast<u32*>(&t);
}
__device__ __forceinline__ void split_pair(float v0, float v1, u32& hw, u32& lw) {
    __nv_bfloat16 h0 = __float2bfloat16(v0), h1 = __float2bfloat16(v1);
    float r0 = v0 - __bfloat162float(h0), r1 = v1 - __bfloat162float(h1);
    __nv_bfloat162 th; th.x = h0; th.y = h1;
    hw = *reinterpret_cast<u32*>(&th);
    lw = packbf(r0, r1);
}
__device__ __forceinline__ void wreduce2(float& s, float& q) {
    #pragma unroll
    for (int o = 16; o > 0; o >>= 1) {
        s += __shfl_xor_sync(0xffffffffu, s, o);
        q += __shfl_xor_sync(0xffffffffu, q, o);
    }
}

#define MMA16816(c, a, b) \
    asm volatile("mma.sync.aligned.m16n8k16.row.col.f32.bf16.bf16.f32 " \
                 "{%0,%1,%2,%3}, {%4,%5,%6,%7}, {%8,%9}, {%0,%1,%2,%3};" \
                 : "+f"((c)[0]), "+f"((c)[1]), "+f"((c)[2]), "+f"((c)[3]) \
                 : "r"((a)[0]), "r"((a)[1]), "r"((a)[2]), "r"((a)[3]), \
                   "r"((b)[0]), "r"((b)[1]))

// ---------------- kernel 1: latent + prepB combo (independent work) ----------------
// prepB gid decomposition puts n in the LOW bits so weight reads are coalesced.
__global__ __launch_bounds__(256) void k_combo(
    const float* __restrict__ noise, const int* __restrict__ label,
    const float* __restrict__ lin_w, const float* __restrict__ bn0_g,
    const float* __restrict__ bn0_b, const float* __restrict__ emb,
    const float* __restrict__ W2h, const float* __restrict__ W2w,
    const float* __restrict__ W3h, const float* __restrict__ W3w)
{
    const int bid = blockIdx.x, tid = threadIdx.x;
    if (bid < 256) {
        // ---- latent ----
        const int ch = bid, b = tid;
        if (ch >= 128) {
            g_latT[ch*256 + b] = emb[label[b]*128 + (ch - 128)];
            return;
        }
        __shared__ float wsm[100];
        if (b < 100) wsm[b] = lin_w[ch*100 + b];
        __syncthreads();
        const float* nr = noise + b*100;
        float z = 0.f;
        #pragma unroll 4
        for (int i = 0; i < 100; i++) z += nr[i]*wsm[i];
        float s = z, q = z*z;
        wreduce2(s, q);
        __shared__ float sp[8], qp[8];
        if ((b & 31) == 0) { sp[b >> 5] = s; qp[b >> 5] = q; }
        __syncthreads();
        float ts = 0.f, tq = 0.f;
        #pragma unroll
        for (int i = 0; i < 8; i++) { ts += sp[i]; tq += qp[i]; }
        float m   = ts*(1.f/256.f);
        float var = tq*(1.f/256.f) - m*m;
        float a   = bn0_g[ch]*rsqrtf(var + 1e-5f);
        float y   = (z - m)*a + bn0_b[ch];
        g_latT[ch*256 + b] = (y >= 0.f) ? y : 0.01f*y;
        return;
    }
    // ---- prepB: weights -> fragment-order bf16 hi/lo (coalesced reads) ----
    int gid = (bid - 256)*256 + tid;
    if (gid < 524288) {                       // W2: 2 br x 64 cp x 4096 n
        int br = gid >> 18, rem = gid & 262143;
        int cp = rem >> 12, n = rem & 4095;
        const float* W = br ? W2w : W2h;      // row-major [ci][4096]
        float v0 = W[(2*cp)*4096 + n];
        float v1 = W[(2*cp + 1)*4096 + n];
        u32 hw, lw; split_pair(v0, v1, hw, lw);
        int ni = n >> 3, ks = cp >> 3, cpl = cp & 7;
        int lane = (n & 7)*4 + (cpl & 3), w = cpl >> 2;
        int addr = ((ni*8 + ks)*32 + lane)*2 + w;
        g_B2f [br][addr] = hw;
        g_B2fl[br][addr] = lw;
    } else {                                  // W3: 2 br x 128 cp x 1024 n
        int g2 = gid - 524288;
        int br = g2 >> 17, rem = g2 & 131071;
        int cp = rem >> 10, n = rem & 1023;
        const float* W = br ? W3w : W3h;      // [ci][1024]
        float v0 = W[(2*cp)*1024 + n];
        float v1 = W[(2*cp + 1)*1024 + n];
        u32 hw, lw; split_pair(v0, v1, hw, lw);
        int ni = n >> 3, ks = cp >> 3, cpl = cp & 7;
        int lane = (n & 7)*4 + (cpl & 3), w = cpl >> 2;
        int addr = ((ni*16 + ks)*32 + lane)*2 + w;
        g_B3f [br][addr] = hw;
        g_B3fl[br][addr] = lw;
    }
}

// ---------------- kernel 2: conv1 GEMMs, all branches (raw) ----------------
__global__ __launch_bounds__(256) void k_gemm1m(
    const float* __restrict__ Wc, const float* __restrict__ Wh,
    const float* __restrict__ Ww)
{
    const int z = blockIdx.z;
    int N; const float* W; float* O;
    if (z == 2) {
        if (blockIdx.x >= 24) return;
        N = 1536; W = Wc; O = g_craw;
    } else {
        N = 2048; W = z ? Ww : Wh; O = g_x1raw[z];
    }
    const int n0 = blockIdx.x*64, b0 = blockIdx.y*64;
    const int tid = threadIdx.x, tx = tid & 15, ty = tid >> 4;
    __shared__ float Xs[16][68], Ws[16][68];
    float acc[4][4] = {};
    for (int k0 = 0; k0 < 256; k0 += 16) {
        __syncthreads();
        for (int i = tid; i < 1024; i += 256) {
            int k = i >> 6, c = i & 63;
            Xs[k][c] = g_latT[(k0+k)*256 + b0 + c];
            Ws[k][c] = W[(k0+k)*N + n0 + c];
        }
        __syncthreads();
        #pragma unroll
        for (int k = 0; k < 16; k++) {
            float4 x4 = *(const float4*)&Xs[k][ty*4];
            float4 w4 = *(const float4*)&Ws[k][tx*4];
            float xa[4] = {x4.x, x4.y, x4.z, x4.w};
            float wa[4] = {w4.x, w4.y, w4.z, w4.w};
            #pragma unroll
            for (int i = 0; i < 4; i++)
                #pragma unroll
                for (int j = 0; j < 4; j++) acc[i][j] += xa[i]*wa[j];
        }
    }
    #pragma unroll
    for (int i = 0; i < 4; i++) {
        float4 v = make_float4(acc[i][0], acc[i][1], acc[i][2], acc[i][3]);
        *(float4*)&O[(b0 + ty*4 + i)*N + n0 + tx*4] = v;
    }
}

// ---------------- kernel 3: BN stats conv1 ----------------
__global__ __launch_bounds__(256) void k_bnstats1(
    const float* __restrict__ cg, const float* __restrict__ cb,
    const float* __restrict__ hg, const float* __restrict__ hb,
    const float* __restrict__ wg, const float* __restrict__ wb)
{
    const int bid = blockIdx.x, b = threadIdx.x;
    float s = 0.f, q = 0.f; float invn; float gam, bet;
    int which, br = 0, co;
    if (bid < 512) {
        which = 0; co = bid;
        const float* p = g_craw + b*1536 + co*3;
        #pragma unroll
        for (int l = 0; l < 3; l++) { float v = p[l]; s += v; q += v*v; }
        invn = 1.f/(256.f*3.f); gam = cg[co]; bet = cb[co];
    } else {
        which = 1; int idx = bid - 512; br = idx >> 7; co = idx & 127;
        const float* p = g_x1raw[br] + b*2048 + co*16;
        #pragma unroll
        for (int l = 0; l < 16; l++) { float v = p[l]; s += v; q += v*v; }
        invn = 1.f/(256.f*16.f);
        gam = br ? wg[co] : hg[co]; bet = br ? wb[co] : hb[co];
    }
    wreduce2(s, q);
    __shared__ float sp[8], qp[8];
    if ((b & 31) == 0) { sp[b >> 5] = s; qp[b >> 5] = q; }
    __syncthreads();
    if (b == 0) {
        float ts = 0.f, tq = 0.f;
        #pragma unroll
        for (int i = 0; i < 8; i++) { ts += sp[i]; tq += qp[i]; }
        float m   = ts*invn;
        float var = tq*invn - m*m;
        float a   = gam*rsqrtf(var + 1e-5f);
        float sh  = bet - m*a;
        if (which == 0) { g_abc[0][co] = a; g_abc[1][co] = sh; }
        else            { g_abhw[br][0][co] = a; g_abhw[br][1][co] = sh; }
    }
}

// ---------------- prepA2: per-batch smem tile, coalesced both ways ----------------
// Also zeroes the conv2 stat accumulators (runs strictly before conv2f).
__global__ __launch_bounds__(256) void k_prepA2n()
{
    const int b = blockIdx.x, br = blockIdx.y, tid = threadIdx.x;
    if (blockIdx.x == 0) {
        ((float*)g_st2[br])[tid]       = 0.f;
        ((float*)g_st2[br])[tid + 256] = 0.f;
    }
    __shared__ float xs[128*17];     // [ci*17 + l], padded
    __shared__ float aAs[128], aSs[128];
    for (int idx = tid; idx < 2048; idx += 256) {
        float v = g_x1raw[br][b*2048 + idx];
        xs[(idx >> 4)*17 + (idx & 15)] = v;
    }
    if (tid < 128) {
        aAs[tid] = g_abhw[br][0][tid];
        aSs[tid] = g_abhw[br][1][tid];
    }
    __syncthreads();
    const int ks = tid >> 5, lane = tid & 31;
    u32 oh[4], ol[4];
    #pragma unroll
    for (int w = 0; w < 4; w++) {
        int cpl2 = w >> 1, l3 = w & 1;
        int l   = (l3 << 3) | (lane >> 2);
        int cpl = (cpl2 << 2) | (lane & 3);
        int ci  = (ks*8 + cpl)*2;
        float v0 = fmaf(aAs[ci],   xs[ci*17 + l],     aSs[ci]);
        float v1 = fmaf(aAs[ci+1], xs[(ci+1)*17 + l], aSs[ci+1]);
        v0 = (v0 >= 0.f) ? v0 : 0.2f*v0;
        v1 = (v1 >= 0.f) ? v1 : 0.2f*v1;
        split_pair(v0, v1, oh[w], ol[w]);
    }
    int addr = ((b*8 + ks)*32 + lane)*4;
    *(uint4*)&g_A2f [br][addr] = make_uint4(oh[0], oh[1], oh[2], oh[3]);
    *(uint4*)&g_A2fl[br][addr] = make_uint4(ol[0], ol[1], ol[2], ol[3]);
}

// ---------------- conv2: fragment-direct mma.sync + fused BN stat partials ----------
extern __shared__ u32 smw[];
__global__ __launch_bounds__(256, 2) void k_conv2f()
{
    const int br = blockIdx.z, nx = blockIdx.x, my = blockIdx.y;
    const int tid = threadIdx.x, lane = tid & 31, wid = tid >> 5;
    const int wm = wid >> 2, wn = wid & 3;
    const u32* __restrict__ AH = g_A2f [br];
    const u32* __restrict__ AL = g_A2fl[br];
    const u32* __restrict__ BH = g_B2f [br];
    const u32* __restrict__ BL = g_B2fl[br];
    const int mi0 = my*8 + wm*4;
    const int ni0 = nx*16 + wn*4;
    float acc[4][4][4] = {};
    #pragma unroll
    for (int ks = 0; ks < 8; ks++) {
        u32 bh[4][2], bl[4][2];
        #pragma unroll
        for (int nt = 0; nt < 4; nt++) {
            int ba = (((ni0+nt)*8 + ks)*32 + lane)*2;
            uint2 vh = *(const uint2*)(BH + ba); bh[nt][0] = vh.x; bh[nt][1] = vh.y;
            uint2 vl = *(const uint2*)(BL + ba); bl[nt][0] = vl.x; bl[nt][1] = vl.y;
        }
        #pragma unroll
        for (int mt = 0; mt < 4; mt++) {
            int aa = (((mi0+mt)*8 + ks)*32 + lane)*4;
            uint4 vh = *(const uint4*)(AH + aa);
            uint4 vl = *(const uint4*)(AL + aa);
            u32 ah[4] = {vh.x, vh.y, vh.z, vh.w};
            u32 al[4] = {vl.x, vl.y, vl.z, vl.w};
            #pragma unroll
            for (int nt = 0; nt < 4; nt++) {
                MMA16816(acc[mt][nt], ah, bh[nt]);
                MMA16816(acc[mt][nt], ah, bl[nt]);
                MMA16816(acc[mt][nt], al, bh[nt]);
            }
        }
    }
    float* Cs = (float*)smw;                    // 128 x 132
    const int qr = lane >> 2, qt = lane & 3;
    #pragma unroll
    for (int mt = 0; mt < 4; mt++)
        #pragma unroll
        for (int nt = 0; nt < 4; nt++) {
            int r0 = wm*64 + mt*16 + qr, c0 = wn*32 + nt*8 + qt*2;
            Cs[r0*132 + c0]       = acc[mt][nt][0];
            Cs[r0*132 + c0 + 1]   = acc[mt][nt][1];
            Cs[(r0+8)*132 + c0]   = acc[mt][nt][2];
            Cs[(r0+8)*132 + c0+1] = acc[mt][nt][3];
        }
    __syncthreads();
    // epilogue: warp w owns output channel co_l = w for all 8 b x 31 t;
    // fold antidiagonals, write y2, and accumulate BN stat partials.
    {
        const int co_l = wid;
        float ssum = 0.f, sq = 0.f;
        for (int i = lane; i < 248; i += 32) {
            int bl2 = i / 31, t = i - bl2*31;
            int lo = (t > 15) ? (t - 15) : 0;
            int hi = (t < 15) ? t : 15;
            float s = 0.f;
            for (int tp = lo; tp <= hi; tp++)
                s += Cs[(bl2*16 + tp)*132 + co_l*16 + (t - tp)];
            g_y2[br][((my*8 + bl2)*256 + nx*8 + co_l)*31 + t] = s;
            ssum += s; sq += s*s;
        }
        wreduce2(ssum, sq);
        if (lane == 0) {
            atomicAdd(&g_st2[br][0][nx*8 + co_l], ssum);
            atomicAdd(&g_st2[br][1][nx*8 + co_l], sq);
        }
    }
}

// ---------------- prepA3: affine from fused stats, smem tile, fragment order ------
__global__ __launch_bounds__(256) void k_prepA3n(
    const float* __restrict__ hg, const float* __restrict__ hb,
    const float* __restrict__ wg, const float* __restrict__ wb)
{
    const int b = blockIdx.x, br = blockIdx.y, tid = threadIdx.x;
    __shared__ float ys[256*33];     // [ci*33 + t], padded
    __shared__ float aAs[256], aSs[256];
    {   // derive BN affine from accumulated stats
        float s = g_st2[br][0][tid], q = g_st2[br][1][tid];
        const float inv = 1.f/(256.f*31.f);
        float m   = s*inv;
        float var = q*inv - m*m;
        float gam = br ? wg[tid] : hg[tid];
        float bet = br ? wb[tid] : hb[tid];
        float a   = gam*rsqrtf(var + 1e-5f);
        aAs[tid] = a;
        aSs[tid] = bet - m*a;
    }
    for (int idx = tid; idx < 7936; idx += 256) {
        float v = g_y2[br][b*7936 + idx];
        ys[(idx / 31)*33 + (idx % 31)] = v;
    }
    __syncthreads();
    const int lane = tid & 31;
    #pragma unroll
    for (int it = 0; it < 2; it++) {
        const int ks = (tid >> 5) + 8*it;
        #pragma unroll
        for (int mih = 0; mih < 2; mih++) {
            u32 oh[4], ol[4];
            #pragma unroll
            for (int w = 0; w < 4; w++) {
                int cpl2 = w >> 1, r3 = w & 1;
                int r   = (r3 << 3) | (lane >> 2);
                int tp  = (mih << 4) | r;
                int cpl = (cpl2 << 2) | (lane & 3);
                int ci  = (ks*8 + cpl)*2;
                float v0 = 0.f, v1 = 0.f;
                if (tp < 31) {
                    v0 = fmaf(aAs[ci],   ys[ci*33 + tp],     aSs[ci]);
                    v1 = fmaf(aAs[ci+1], ys[(ci+1)*33 + tp], aSs[ci+1]);
                    v0 = (v0 >= 0.f) ? v0 : 0.2f*v0;
                    v1 = (v1 >= 0.f) ? v1 : 0.2f*v1;
                }
                split_pair(v0, v1, oh[w], ol[w]);
            }
            int mi = b*2 + mih;
            int addr = ((mi*16 + ks)*32 + lane)*4;
            *(uint4*)&g_A3f [br][addr] = make_uint4(oh[0], oh[1], oh[2], oh[3]);
            *(uint4*)&g_A3fl[br][addr] = make_uint4(ol[0], ol[1], ol[2], ol[3]);
        }
    }
}

// ---------------- conv3: fragment-direct mma.sync, fold + bias + tanh ------
__global__ __launch_bounds__(256, 2) void k_conv3f(
    const float* __restrict__ bh3, const float* __restrict__ bw3)
{
    const int br = blockIdx.z, nx = blockIdx.x, my = blockIdx.y;
    const float* __restrict__ bias = br ? bw3 : bh3;
    const int tid = threadIdx.x, lane = tid & 31, wid = tid >> 5;
    const int wm = wid >> 2, wn = wid & 3;
    const u32* __restrict__ AH = g_A3f [br];
    const u32* __restrict__ AL = g_A3fl[br];
    const u32* __restrict__ BH = g_B3f [br];
    const u32* __restrict__ BL = g_B3fl[br];
    const int mi0 = my*8 + wm*4;
    const int ni0 = nx*16 + wn*4;
    float acc[4][4][4] = {};
    #pragma unroll
    for (int ks = 0; ks < 16; ks++) {
        u32 bh[4][2], bl[4][2];
        #pragma unroll
        for (int nt = 0; nt < 4; nt++) {
            int ba = (((ni0+nt)*16 + ks)*32 + lane)*2;
            uint2 vh = *(const uint2*)(BH + ba); bh[nt][0] = vh.x; bh[nt][1] = vh.y;
            uint2 vl = *(const uint2*)(BL + ba); bl[nt][0] = vl.x; bl[nt][1] = vl.y;
        }
        #pragma unroll
        for (int mt = 0; mt < 4; mt++) {
            int aa = (((mi0+mt)*16 + ks)*32 + lane)*4;
            uint4 vh = *(const uint4*)(AH + aa);
            uint4 vl = *(const uint4*)(AL + aa);
            u32 ah[4] = {vh.x, vh.y, vh.z, vh.w};
            u32 al[4] = {vl.x, vl.y, vl.z, vl.w};
            #pragma unroll
            for (int nt = 0; nt < 4; nt++) {
                MMA16816(acc[mt][nt], ah, bh[nt]);
                MMA16816(acc[mt][nt], ah, bl[nt]);
                MMA16816(acc[mt][nt], al, bh[nt]);
            }
        }
    }
    float* Cs = (float*)smw;                    // 128 x 132
    const int qr = lane >> 2, qt = lane & 3;
    #pragma unroll
    for (int mt = 0; mt < 4; mt++)
        #pragma unroll
        for (int nt = 0; nt < 4; nt++) {
            int r0 = wm*64 + mt*16 + qr, c0 = wn*32 + nt*8 + qt*2;
            Cs[r0*132 + c0]       = acc[mt][nt][0];
            Cs[r0*132 + c0 + 1]   = acc[mt][nt][1];
            Cs[(r0+8)*132 + c0]   = acc[mt][nt][2];
            Cs[(r0+8)*132 + c0+1] = acc[mt][nt][3];
        }
    __syncthreads();
    // rows: bl*32 + t' (4 b per CTA), cols: co_l*2 + k (64 co per CTA)
    for (int i = 0; i < 32; i++) {
        int idx = tid + i*256;                  // 8192 outputs
        int t = idx & 31, co_l = (idx >> 5) & 63, bl2 = idx >> 11;
        int row = bl2*32 + t;
        float v = Cs[row*132 + 2*co_l];
        if (t > 0) v += Cs[(row-1)*132 + 2*co_l + 1];
        v += bias[nx*64 + co_l];
        g_hw[br][((my*4 + bl2)*512 + nx*64 + co_l)*32 + t] = tanhf(v);
    }
}

// ---------------- kernel: final einsum ----------------
__global__ __launch_bounds__(256) void k_final(const float* __restrict__ coef,
                                               float* __restrict__ out)
{
    const int b = blockIdx.x, tid = threadIdx.x;
    __shared__ __align__(16) float4 cs[128];
    __shared__ __align__(16) float  hs [128*32];
    __shared__ __align__(16) float  ws2[128*32];
    const int p0 = tid*4, hh = p0 >> 5, ww0 = p0 & 31;
    float acc[4][3];
    #pragma unroll
    for (int i = 0; i < 4; i++)
        #pragma unroll
        for (int c = 0; c < 3; c++) acc[i][c] = 0.f;
    for (int chk = 0; chk < 4; chk++) {
        const int r0 = chk*128;
        __syncthreads();
        if (tid < 128) {
            const int r = r0 + tid;
            const float* cp = g_craw + b*1536 + r*3;
            float a = g_abc[0][r], sh = g_abc[1][r];
            float cf = coef[r];
            float v0 = fmaf(a, cp[0], sh); v0 = (v0 >= 0.f) ? v0 : 0.2f*v0;
            float v1 = fmaf(a, cp[1], sh); v1 = (v1 >= 0.f) ? v1 : 0.2f*v1;
            float v2 = fmaf(a, cp[2], sh); v2 = (v2 >= 0.f) ? v2 : 0.2f*v2;
            cs[tid] = make_float4(v0*cf, v1*cf, v2*cf, 0.f);
        }
        for (int idx = tid; idx < 4096; idx += 256) {
            hs [idx] = g_hw[0][(b*512 + r0)*32 + idx];
            ws2[idx] = g_hw[1][(b*512 + r0)*32 + idx];
        }
        __syncthreads();
        for (int r = 0; r < 128; r++) {
            float4 c4 = cs[r];
            float  hv = hs[r*32 + hh];
            float4 wv = *reinterpret_cast<const float4*>(&ws2[r*32 + ww0]);
            float p;
            p = hv*wv.x; acc[0][0] += p*c4.x; acc[0][1] += p*c4.y; acc[0][2] += p*c4.z;
            p = hv*wv.y; acc[1][0] += p*c4.x; acc[1][1] += p*c4.y; acc[1][2] += p*c4.z;
            p = hv*wv.z; acc[2][0] += p*c4.x; acc[2][1] += p*c4.y; acc[2][2] += p*c4.z;
            p = hv*wv.w; acc[3][0] += p*c4.x; acc[3][1] += p*c4.y; acc[3][2] += p*c4.z;
        }
    }
    #pragma unroll
    for (int c = 0; c < 3; c++)
        #pragma unroll
        for (int i = 0; i < 4; i++)
            out[((b*3 + c)*32 + hh)*32 + ww0 + i] = acc[i][c];
}

// ---------------- launch ----------------
extern "C" void kernel_launch(void* const* d_in, const int* in_sizes, int n_in,
                              void* d_out, int out_size)
{
    const float* noise = (const float*)d_in[0];
    const int*   label = (const int*)  d_in[1];
    const float* lin_w = (const float*)d_in[2];
    const float* bn0_g = (const float*)d_in[4];
    const float* bn0_b = (const float*)d_in[5];
    const float* emb   = (const float*)d_in[6];
    const float* c_w1  = (const float*)d_in[7];
    const float* c_g1  = (const float*)d_in[9];
    const float* c_be1 = (const float*)d_in[10];
    const float* h_w1  = (const float*)d_in[11];
    const float* h_g1  = (const float*)d_in[13];
    const float* h_be1 = (const float*)d_in[14];
    const float* h_w2  = (const float*)d_in[15];
    const float* h_g2  = (const float*)d_in[17];
    const float* h_be2 = (const float*)d_in[18];
    const float* h_w3  = (const float*)d_in[19];
    const float* h_b3  = (const float*)d_in[20];
    const float* w_w1  = (const float*)d_in[21];
    const float* w_g1  = (const float*)d_in[23];
    const float* w_be1 = (const float*)d_in[24];
    const float* w_w2  = (const float*)d_in[25];
    const float* w_g2  = (const float*)d_in[27];
    const float* w_be2 = (const float*)d_in[28];
    const float* w_w3  = (const float*)d_in[29];
    const float* w_b3  = (const float*)d_in[30];
    const float* coef  = (const float*)d_in[31];
    float* out = (float*)d_out;

    const int SMEM = 128*132*4;  // 67584 B (epilogue C buffer)
    cudaFuncSetAttribute(k_conv2f, cudaFuncAttributeMaxDynamicSharedMemorySize, SMEM);
    cudaFuncSetAttribute(k_conv3f, cudaFuncAttributeMaxDynamicSharedMemorySize, SMEM);

    k_combo<<<3328, 256>>>(noise, label, lin_w, bn0_g, bn0_b, emb,
                           h_w2, w_w2, h_w3, w_w3);

    k_gemm1m<<<dim3(32, 4, 3), 256>>>(c_w1, h_w1, w_w1);

    k_bnstats1<<<768, 256>>>(c_g1, c_be1, h_g1, h_be1, w_g1, w_be1);

    k_prepA2n<<<dim3(256, 2), 256>>>();

    k_conv2f<<<dim3(32, 32, 2), 256, SMEM>>>();

    k_prepA3n<<<dim3(256, 2), 256>>>(h_g2, h_be2, w_g2, w_be2);

    k_conv3f<<<dim3(8, 64, 2), 256, SMEM>>>(h_b3, w_b3);

    k_final<<<256, 256>>>(coef, out);
}

// round 15
// speedup vs baseline: 1.6482x; 1.0118x over previous
#include <cuda_runtime.h>
#include <cuda_bf16.h>
#include <math.h>
#include <stdint.h>

typedef uint32_t u32;

// ---------------- scratch (device globals; no allocation) ----------------
__device__ float g_latT [256*256];
__device__ float g_craw [256*1536];
__device__ float g_x1raw[2][256*2048];
__device__ float g_y2   [2][256*256*31];
__device__ float g_abc  [2][512];
__device__ float g_st1c [2][512];           // conv1 c-branch stat accumulators
__device__ float g_st1hw[2][2][128];        // conv1 h/w stat accumulators
__device__ float g_st2  [2][2][256];        // conv2 stat accumulators
__device__ float g_hw   [2][256*512*32];
// fragment-order bf16 operands: A [mi][ks][lane][4 words], B [ni][ks][lane][2 words]
__device__ __align__(16) u32 g_A2f [2][256*8*32*4];
__device__ __align__(16) u32 g_A2fl[2][256*8*32*4];
__device__ __align__(16) u32 g_B2f [2][512*8*32*2];
__device__ __align__(16) u32 g_B2fl[2][512*8*32*2];
__device__ __align__(16) u32 g_A3f [2][512*16*32*4];
__device__ __align__(16) u32 g_A3fl[2][512*16*32*4];
__device__ __align__(16) u32 g_B3f [2][128*16*32*2];
__device__ __align__(16) u32 g_B3fl[2][128*16*32*2];

__device__ __forceinline__ u32 packbf(float x, float y) {
    __nv_bfloat162 t;
    t.x = __float2bfloat16(x);
    t.y = __float2bfloat16(y);
    return *reinterpret_cast<u32*>(&t);
}
__device__ __forceinline__ void split_pair(float v0, float v1, u32& hw, u32& lw) {
    __nv_bfloat16 h0 = __float2bfloat16(v0), h1 = __float2bfloat16(v1);
    float r0 = v0 - __bfloat162float(h0), r1 = v1 - __bfloat162float(h1);
    __nv_bfloat162 th; th.x = h0; th.y = h1;
    hw = *reinterpret_cast<u32*>(&th);
    lw = packbf(r0, r1);
}
__device__ __forceinline__ void wreduce2(float& s, float& q) {
    #pragma unroll
    for (int o = 16; o > 0; o >>= 1) {
        s += __shfl_xor_sync(0xffffffffu, s, o);
        q += __shfl_xor_sync(0xffffffffu, q, o);
    }
}

#define MMA16816(c, a, b) \
    asm volatile("mma.sync.aligned.m16n8k16.row.col.f32.bf16.bf16.f32 " \
                 "{%0,%1,%2,%3}, {%4,%5,%6,%7}, {%8,%9}, {%0,%1,%2,%3};" \
                 : "+f"((c)[0]), "+f"((c)[1]), "+f"((c)[2]), "+f"((c)[3]) \
                 : "r"((a)[0]), "r"((a)[1]), "r"((a)[2]), "r"((a)[3]), \
                   "r"((b)[0]), "r"((b)[1]))

// ---------------- kernel 1: latent + prepB combo (independent work) ----------------
__global__ __launch_bounds__(256) void k_combo(
    const float* __restrict__ noise, const int* __restrict__ label,
    const float* __restrict__ lin_w, const float* __restrict__ bn0_g,
    const float* __restrict__ bn0_b, const float* __restrict__ emb,
    const float* __restrict__ W2h, const float* __restrict__ W2w,
    const float* __restrict__ W3h, const float* __restrict__ W3w)
{
    const int bid = blockIdx.x, tid = threadIdx.x;
    if (bid < 256) {
        if (bid == 0) {   // zero all stat accumulators (before any producer runs)
            float* p1 = (float*)g_st1c;
            for (int i = tid; i < 1024; i += 256) p1[i] = 0.f;
            float* p2 = (float*)g_st1hw;
            for (int i = tid; i < 512; i += 256) p2[i] = 0.f;
            float* p3 = (float*)g_st2;
            for (int i = tid; i < 1024; i += 256) p3[i] = 0.f;
        }
        // ---- latent ----
        const int ch = bid, b = tid;
        if (ch >= 128) {
            g_latT[ch*256 + b] = emb[label[b]*128 + (ch - 128)];
            return;
        }
        __shared__ float wsm[100];
        if (b < 100) wsm[b] = lin_w[ch*100 + b];
        __syncthreads();
        const float* nr = noise + b*100;
        float z = 0.f;
        #pragma unroll 4
        for (int i = 0; i < 100; i++) z += nr[i]*wsm[i];
        float s = z, q = z*z;
        wreduce2(s, q);
        __shared__ float sp[8], qp[8];
        if ((b & 31) == 0) { sp[b >> 5] = s; qp[b >> 5] = q; }
        __syncthreads();
        float ts = 0.f, tq = 0.f;
        #pragma unroll
        for (int i = 0; i < 8; i++) { ts += sp[i]; tq += qp[i]; }
        float m   = ts*(1.f/256.f);
        float var = tq*(1.f/256.f) - m*m;
        float a   = bn0_g[ch]*rsqrtf(var + 1e-5f);
        float y   = (z - m)*a + bn0_b[ch];
        g_latT[ch*256 + b] = (y >= 0.f) ? y : 0.01f*y;
        return;
    }
    // ---- prepB: weights -> fragment-order bf16 hi/lo (coalesced reads) ----
    int gid = (bid - 256)*256 + tid;
    if (gid < 524288) {                       // W2: 2 br x 64 cp x 4096 n
        int br = gid >> 18, rem = gid & 262143;
        int cp = rem >> 12, n = rem & 4095;
        const float* W = br ? W2w : W2h;      // row-major [ci][4096]
        float v0 = W[(2*cp)*4096 + n];
        float v1 = W[(2*cp + 1)*4096 + n];
        u32 hw, lw; split_pair(v0, v1, hw, lw);
        int ni = n >> 3, ks = cp >> 3, cpl = cp & 7;
        int lane = (n & 7)*4 + (cpl & 3), w = cpl >> 2;
        int addr = ((ni*8 + ks)*32 + lane)*2 + w;
        g_B2f [br][addr] = hw;
        g_B2fl[br][addr] = lw;
    } else {                                  // W3: 2 br x 128 cp x 1024 n
        int g2 = gid - 524288;
        int br = g2 >> 17, rem = g2 & 131071;
        int cp = rem >> 10, n = rem & 1023;
        const float* W = br ? W3w : W3h;      // [ci][1024]
        float v0 = W[(2*cp)*1024 + n];
        float v1 = W[(2*cp + 1)*1024 + n];
        u32 hw, lw; split_pair(v0, v1, hw, lw);
        int ni = n >> 3, ks = cp >> 3, cpl = cp & 7;
        int lane = (n & 7)*4 + (cpl & 3), w = cpl >> 2;
        int addr = ((ni*16 + ks)*32 + lane)*2 + w;
        g_B3f [br][addr] = hw;
        g_B3fl[br][addr] = lw;
    }
}

// ---------------- kernel 2: conv1 GEMMs + fused BN stat partials ----------------
__global__ __launch_bounds__(256) void k_gemm1m(
    const float* __restrict__ Wc, const float* __restrict__ Wh,
    const float* __restrict__ Ww)
{
    const int z = blockIdx.z;
    int N; const float* W; float* O;
    if (z == 2) {
        if (blockIdx.x >= 24) return;
        N = 1536; W = Wc; O = g_craw;
    } else {
        N = 2048; W = z ? Ww : Wh; O = g_x1raw[z];
    }
    const int n0 = blockIdx.x*64, b0 = blockIdx.y*64;
    const int tid = threadIdx.x, tx = tid & 15, ty = tid >> 4;
    __shared__ float Xs[16][68], Ws[16][68];
    __shared__ float cs1[64], cq1[64];
    if (tid < 64) { cs1[tid] = 0.f; cq1[tid] = 0.f; }
    float acc[4][4] = {};
    for (int k0 = 0; k0 < 256; k0 += 16) {
        __syncthreads();
        for (int i = tid; i < 1024; i += 256) {
            int k = i >> 6, c = i & 63;
            Xs[k][c] = g_latT[(k0+k)*256 + b0 + c];
            Ws[k][c] = W[(k0+k)*N + n0 + c];
        }
        __syncthreads();
        #pragma unroll
        for (int k = 0; k < 16; k++) {
            float4 x4 = *(const float4*)&Xs[k][ty*4];
            float4 w4 = *(const float4*)&Ws[k][tx*4];
            float xa[4] = {x4.x, x4.y, x4.z, x4.w};
            float wa[4] = {w4.x, w4.y, w4.z, w4.w};
            #pragma unroll
            for (int i = 0; i < 4; i++)
                #pragma unroll
                for (int j = 0; j < 4; j++) acc[i][j] += xa[i]*wa[j];
        }
    }
    #pragma unroll
    for (int i = 0; i < 4; i++) {
        float4 v = make_float4(acc[i][0], acc[i][1], acc[i][2], acc[i][3]);
        *(float4*)&O[(b0 + ty*4 + i)*N + n0 + tx*4] = v;
    }
    // fused per-channel stat partials
    #pragma unroll
    for (int j = 0; j < 4; j++) {
        float s = acc[0][j] + acc[1][j] + acc[2][j] + acc[3][j];
        float q = acc[0][j]*acc[0][j] + acc[1][j]*acc[1][j]
                + acc[2][j]*acc[2][j] + acc[3][j]*acc[3][j];
        atomicAdd(&cs1[tx*4 + j], s);
        atomicAdd(&cq1[tx*4 + j], q);
    }
    __syncthreads();
    if (tid < 64) {
        int n = n0 + tid;
        if (z == 2) {
            atomicAdd(&g_st1c[0][n/3], cs1[tid]);
            atomicAdd(&g_st1c[1][n/3], cq1[tid]);
        } else {
            atomicAdd(&g_st1hw[z][0][n >> 4], cs1[tid]);
            atomicAdd(&g_st1hw[z][1][n >> 4], cq1[tid]);
        }
    }
}

// ---------------- prepA2: affine from fused stats, smem tile, fragment order --------
// Block (1, 0) additionally materializes the c-branch affine (g_abc) for k_final.
__global__ __launch_bounds__(256) void k_prepA2n(
    const float* __restrict__ cg, const float* __restrict__ cb,
    const float* __restrict__ hg, const float* __restrict__ hb,
    const float* __restrict__ wg, const float* __restrict__ wb)
{
    const int b = blockIdx.x, br = blockIdx.y, tid = threadIdx.x;
    if (b == 1 && br == 0) {
        for (int c = tid; c < 512; c += 256) {
            float s = g_st1c[0][c], q = g_st1c[1][c];
            const float invn = 1.f/(256.f*3.f);
            float m   = s*invn;
            float var = q*invn - m*m;
            float a   = cg[c]*rsqrtf(var + 1e-5f);
            g_abc[0][c] = a;
            g_abc[1][c] = cb[c] - m*a;
        }
    }
    __shared__ float xs[128*17];     // [ci*17 + l], padded
    __shared__ float aAs[128], aSs[128];
    if (tid < 128) {
        float s = g_st1hw[br][0][tid], q = g_st1hw[br][1][tid];
        const float invn = 1.f/(256.f*16.f);
        float m   = s*invn;
        float var = q*invn - m*m;
        float gam = br ? wg[tid] : hg[tid];
        float bet = br ? wb[tid] : hb[tid];
        float a   = gam*rsqrtf(var + 1e-5f);
        aAs[tid] = a;
        aSs[tid] = bet - m*a;
    }
    for (int idx = tid; idx < 2048; idx += 256) {
        float v = g_x1raw[br][b*2048 + idx];
        xs[(idx >> 4)*17 + (idx & 15)] = v;
    }
    __syncthreads();
    const int ks = tid >> 5, lane = tid & 31;
    u32 oh[4], ol[4];
    #pragma unroll
    for (int w = 0; w < 4; w++) {
        int cpl2 = w >> 1, l3 = w & 1;
        int l   = (l3 << 3) | (lane >> 2);
        int cpl = (cpl2 << 2) | (lane & 3);
        int ci  = (ks*8 + cpl)*2;
        float v0 = fmaf(aAs[ci],   xs[ci*17 + l],     aSs[ci]);
        float v1 = fmaf(aAs[ci+1], xs[(ci+1)*17 + l], aSs[ci+1]);
        v0 = (v0 >= 0.f) ? v0 : 0.2f*v0;
        v1 = (v1 >= 0.f) ? v1 : 0.2f*v1;
        split_pair(v0, v1, oh[w], ol[w]);
    }
    int addr = ((b*8 + ks)*32 + lane)*4;
    *(uint4*)&g_A2f [br][addr] = make_uint4(oh[0], oh[1], oh[2], oh[3]);
    *(uint4*)&g_A2fl[br][addr] = make_uint4(ol[0], ol[1], ol[2], ol[3]);
}

// ---------------- conv2: fragment-direct mma.sync + fused BN stat partials ----------
extern __shared__ u32 smw[];
__global__ __launch_bounds__(256, 2) void k_conv2f()
{
    const int br = blockIdx.z, nx = blockIdx.x, my = blockIdx.y;
    const int tid = threadIdx.x, lane = tid & 31, wid = tid >> 5;
    const int wm = wid >> 2, wn = wid & 3;
    const u32* __restrict__ AH = g_A2f [br];
    const u32* __restrict__ AL = g_A2fl[br];
    const u32* __restrict__ BH = g_B2f [br];
    const u32* __restrict__ BL = g_B2fl[br];
    const int mi0 = my*8 + wm*4;
    const int ni0 = nx*16 + wn*4;
    float acc[4][4][4] = {};
    #pragma unroll
    for (int ks = 0; ks < 8; ks++) {
        u32 bh[4][2], bl[4][2];
        #pragma unroll
        for (int nt = 0; nt < 4; nt++) {
            int ba = (((ni0+nt)*8 + ks)*32 + lane)*2;
            uint2 vh = *(const uint2*)(BH + ba); bh[nt][0] = vh.x; bh[nt][1] = vh.y;
            uint2 vl = *(const uint2*)(BL + ba); bl[nt][0] = vl.x; bl[nt][1] = vl.y;
        }
        #pragma unroll
        for (int mt = 0; mt < 4; mt++) {
            int aa = (((mi0+mt)*8 + ks)*32 + lane)*4;
            uint4 vh = *(const uint4*)(AH + aa);
            uint4 vl = *(const uint4*)(AL + aa);
            u32 ah[4] = {vh.x, vh.y, vh.z, vh.w};
            u32 al[4] = {vl.x, vl.y, vl.z, vl.w};
            #pragma unroll
            for (int nt = 0; nt < 4; nt++) {
                MMA16816(acc[mt][nt], ah, bh[nt]);
                MMA16816(acc[mt][nt], ah, bl[nt]);
                MMA16816(acc[mt][nt], al, bh[nt]);
            }
        }
    }
    float* Cs = (float*)smw;                    // 128 x 132
    const int qr = lane >> 2, qt = lane & 3;
    #pragma unroll
    for (int mt = 0; mt < 4; mt++)
        #pragma unroll
        for (int nt = 0; nt < 4; nt++) {
            int r0 = wm*64 + mt*16 + qr, c0 = wn*32 + nt*8 + qt*2;
            Cs[r0*132 + c0]       = acc[mt][nt][0];
            Cs[r0*132 + c0 + 1]   = acc[mt][nt][1];
            Cs[(r0+8)*132 + c0]   = acc[mt][nt][2];
            Cs[(r0+8)*132 + c0+1] = acc[mt][nt][3];
        }
    __syncthreads();
    // epilogue: warp w owns output channel co_l = w; fold, write y2, stat partials.
    {
        const int co_l = wid;
        float ssum = 0.f, sq = 0.f;
        for (int i = lane; i < 248; i += 32) {
            int bl2 = i / 31, t = i - bl2*31;
            int lo = (t > 15) ? (t - 15) : 0;
            int hi = (t < 15) ? t : 15;
            float s = 0.f;
            for (int tp = lo; tp <= hi; tp++)
                s += Cs[(bl2*16 + tp)*132 + co_l*16 + (t - tp)];
            g_y2[br][((my*8 + bl2)*256 + nx*8 + co_l)*31 + t] = s;
            ssum += s; sq += s*s;
        }
        wreduce2(ssum, sq);
        if (lane == 0) {
            atomicAdd(&g_st2[br][0][nx*8 + co_l], ssum);
            atomicAdd(&g_st2[br][1][nx*8 + co_l], sq);
        }
    }
}

// ---------------- prepA3: affine from fused stats, smem tile, fragment order ------
__global__ __launch_bounds__(256) void k_prepA3n(
    const float* __restrict__ hg, const float* __restrict__ hb,
    const float* __restrict__ wg, const float* __restrict__ wb)
{
    const int b = blockIdx.x, br = blockIdx.y, tid = threadIdx.x;
    __shared__ float ys[256*33];     // [ci*33 + t], padded
    __shared__ float aAs[256], aSs[256];
    {   // derive BN affine from accumulated stats
        float s = g_st2[br][0][tid], q = g_st2[br][1][tid];
        const float inv = 1.f/(256.f*31.f);
        float m   = s*inv;
        float var = q*inv - m*m;
        float gam = br ? wg[tid] : hg[tid];
        float bet = br ? wb[tid] : hb[tid];
        float a   = gam*rsqrtf(var + 1e-5f);
        aAs[tid] = a;
        aSs[tid] = bet - m*a;
    }
    for (int idx = tid; idx < 7936; idx += 256) {
        float v = g_y2[br][b*7936 + idx];
        ys[(idx / 31)*33 + (idx % 31)] = v;
    }
    __syncthreads();
    const int lane = tid & 31;
    #pragma unroll
    for (int it = 0; it < 2; it++) {
        const int ks = (tid >> 5) + 8*it;
        #pragma unroll
        for (int mih = 0; mih < 2; mih++) {
            u32 oh[4], ol[4];
            #pragma unroll
            for (int w = 0; w < 4; w++) {
                int cpl2 = w >> 1, r3 = w & 1;
                int r   = (r3 << 3) | (lane >> 2);
                int tp  = (mih << 4) | r;
                int cpl = (cpl2 << 2) | (lane & 3);
                int ci  = (ks*8 + cpl)*2;
                float v0 = 0.f, v1 = 0.f;
                if (tp < 31) {
                    v0 = fmaf(aAs[ci],   ys[ci*33 + tp],     aSs[ci]);
                    v1 = fmaf(aAs[ci+1], ys[(ci+1)*33 + tp], aSs[ci+1]);
                    v0 = (v0 >= 0.f) ? v0 : 0.2f*v0;
                    v1 = (v1 >= 0.f) ? v1 : 0.2f*v1;
                }
                split_pair(v0, v1, oh[w], ol[w]);
            }
            int mi = b*2 + mih;
            int addr = ((mi*16 + ks)*32 + lane)*4;
            *(uint4*)&g_A3f [br][addr] = make_uint4(oh[0], oh[1], oh[2], oh[3]);
            *(uint4*)&g_A3fl[br][addr] = make_uint4(ol[0], ol[1], ol[2], ol[3]);
        }
    }
}

// ---------------- conv3: fragment-direct mma.sync, fold + bias + tanh ------
__global__ __launch_bounds__(256, 2) void k_conv3f(
    const float* __restrict__ bh3, const float* __restrict__ bw3)
{
    const int br = blockIdx.z, nx = blockIdx.x, my = blockIdx.y;
    const float* __restrict__ bias = br ? bw3 : bh3;
    const int tid = threadIdx.x, lane = tid & 31, wid = tid >> 5;
    const int wm = wid >> 2, wn = wid & 3;
    const u32* __restrict__ AH = g_A3f [br];
    const u32* __restrict__ AL = g_A3fl[br];
    const u32* __restrict__ BH = g_B3f [br];
    const u32* __restrict__ BL = g_B3fl[br];
    const int mi0 = my*8 + wm*4;
    const int ni0 = nx*16 + wn*4;
    float acc[4][4][4] = {};
    #pragma unroll
    for (int ks = 0; ks < 16; ks++) {
        u32 bh[4][2], bl[4][2];
        #pragma unroll
        for (int nt = 0; nt < 4; nt++) {
            int ba = (((ni0+nt)*16 + ks)*32 + lane)*2;
            uint2 vh = *(const uint2*)(BH + ba); bh[nt][0] = vh.x; bh[nt][1] = vh.y;
            uint2 vl = *(const uint2*)(BL + ba); bl[nt][0] = vl.x; bl[nt][1] = vl.y;
        }
        #pragma unroll
        for (int mt = 0; mt < 4; mt++) {
            int aa = (((mi0+mt)*16 + ks)*32 + lane)*4;
            uint4 vh = *(const uint4*)(AH + aa);
            uint4 vl = *(const uint4*)(AL + aa);
            u32 ah[4] = {vh.x, vh.y, vh.z, vh.w};
            u32 al[4] = {vl.x, vl.y, vl.z, vl.w};
            #pragma unroll
            for (int nt = 0; nt < 4; nt++) {
                MMA16816(acc[mt][nt], ah, bh[nt]);
                MMA16816(acc[mt][nt], ah, bl[nt]);
                MMA16816(acc[mt][nt], al, bh[nt]);
            }
        }
    }
    float* Cs = (float*)smw;                    // 128 x 132
    const int qr = lane >> 2, qt = lane & 3;
    #pragma unroll
    for (int mt = 0; mt < 4; mt++)
        #pragma unroll
        for (int nt = 0; nt < 4; nt++) {
            int r0 = wm*64 + mt*16 + qr, c0 = wn*32 + nt*8 + qt*2;
            Cs[r0*132 + c0]       = acc[mt][nt][0];
            Cs[r0*132 + c0 + 1]   = acc[mt][nt][1];
            Cs[(r0+8)*132 + c0]   = acc[mt][nt][2];
            Cs[(r0+8)*132 + c0+1] = acc[mt][nt][3];
        }
    __syncthreads();
    // rows: bl*32 + t' (4 b per CTA), cols: co_l*2 + k (64 co per CTA)
    for (int i = 0; i < 32; i++) {
        int idx = tid + i*256;                  // 8192 outputs
        int t = idx & 31, co_l = (idx >> 5) & 63, bl2 = idx >> 11;
        int row = bl2*32 + t;
        float v = Cs[row*132 + 2*co_l];
        if (t > 0) v += Cs[(row-1)*132 + 2*co_l + 1];
        v += bias[nx*64 + co_l];
        g_hw[br][((my*4 + bl2)*512 + nx*64 + co_l)*32 + t] = tanhf(v);
    }
}

// ---------------- kernel: final einsum ----------------
__global__ __launch_bounds__(256) void k_final(const float* __restrict__ coef,
                                               float* __restrict__ out)
{
    const int b = blockIdx.x, tid = threadIdx.x;
    __shared__ __align__(16) float4 cs[128];
    __shared__ __align__(16) float  hs [128*32];
    __shared__ __align__(16) float  ws2[128*32];
    const int p0 = tid*4, hh = p0 >> 5, ww0 = p0 & 31;
    float acc[4][3];
    #pragma unroll
    for (int i = 0; i < 4; i++)
        #pragma unroll
        for (int c = 0; c < 3; c++) acc[i][c] = 0.f;
    for (int chk = 0; chk < 4; chk++) {
        const int r0 = chk*128;
        __syncthreads();
        if (tid < 128) {
            const int r = r0 + tid;
            const float* cp = g_craw + b*1536 + r*3;
            float a = g_abc[0][r], sh = g_abc[1][r];
            float cf = coef[r];
            float v0 = fmaf(a, cp[0], sh); v0 = (v0 >= 0.f) ? v0 : 0.2f*v0;
            float v1 = fmaf(a, cp[1], sh); v1 = (v1 >= 0.f) ? v1 : 0.2f*v1;
            float v2 = fmaf(a, cp[2], sh); v2 = (v2 >= 0.f) ? v2 : 0.2f*v2;
            cs[tid] = make_float4(v0*cf, v1*cf, v2*cf, 0.f);
        }
        for (int idx = tid; idx < 4096; idx += 256) {
            hs [idx] = g_hw[0][(b*512 + r0)*32 + idx];
            ws2[idx] = g_hw[1][(b*512 + r0)*32 + idx];
        }
        __syncthreads();
        for (int r = 0; r < 128; r++) {
            float4 c4 = cs[r];
            float  hv = hs[r*32 + hh];
            float4 wv = *reinterpret_cast<const float4*>(&ws2[r*32 + ww0]);
            float p;
            p = hv*wv.x; acc[0][0] += p*c4.x; acc[0][1] += p*c4.y; acc[0][2] += p*c4.z;
            p = hv*wv.y; acc[1][0] += p*c4.x; acc[1][1] += p*c4.y; acc[1][2] += p*c4.z;
            p = hv*wv.z; acc[2][0] += p*c4.x; acc[2][1] += p*c4.y; acc[2][2] += p*c4.z;
            p = hv*wv.w; acc[3][0] += p*c4.x; acc[3][1] += p*c4.y; acc[3][2] += p*c4.z;
        }
    }
    #pragma unroll
    for (int c = 0; c < 3; c++)
        #pragma unroll
        for (int i = 0; i < 4; i++)
            out[((b*3 + c)*32 + hh)*32 + ww0 + i] = acc[i][c];
}

// ---------------- launch ----------------
extern "C" void kernel_launch(void* const* d_in, const int* in_sizes, int n_in,
                              void* d_out, int out_size)
{
    const float* noise = (const float*)d_in[0];
    const int*   label = (const int*)  d_in[1];
    const float* lin_w = (const float*)d_in[2];
    const float* bn0_g = (const float*)d_in[4];
    const float* bn0_b = (const float*)d_in[5];
    const float* emb   = (const float*)d_in[6];
    const float* c_w1  = (const float*)d_in[7];
    const float* c_g1  = (const float*)d_in[9];
    const float* c_be1 = (const float*)d_in[10];
    const float* h_w1  = (const float*)d_in[11];
    const float* h_g1  = (const float*)d_in[13];
    const float* h_be1 = (const float*)d_in[14];
    const float* h_w2  = (const float*)d_in[15];
    const float* h_g2  = (const float*)d_in[17];
    const float* h_be2 = (const float*)d_in[18];
    const float* h_w3  = (const float*)d_in[19];
    const float* h_b3  = (const float*)d_in[20];
    const float* w_w1  = (const float*)d_in[21];
    const float* w_g1  = (const float*)d_in[23];
    const float* w_be1 = (const float*)d_in[24];
    const float* w_w2  = (const float*)d_in[25];
    const float* w_g2  = (const float*)d_in[27];
    const float* w_be2 = (const float*)d_in[28];
    const float* w_w3  = (const float*)d_in[29];
    const float* w_b3  = (const float*)d_in[30];
    const float* coef  = (const float*)d_in[31];
    float* out = (float*)d_out;

    const int SMEM = 128*132*4;  // 67584 B (epilogue C buffer)
    cudaFuncSetAttribute(k_conv2f, cudaFuncAttributeMaxDynamicSharedMemorySize, SMEM);
    cudaFuncSetAttribute(k_conv3f, cudaFuncAttributeMaxDynamicSharedMemorySize, SMEM);

    k_combo<<<3328, 256>>>(noise, label, lin_w, bn0_g, bn0_b, emb,
                           h_w2, w_w2, h_w3, w_w3);

    k_gemm1m<<<dim3(32, 4, 3), 256>>>(c_w1, h_w1, w_w1);

    k_prepA2n<<<dim3(256, 2), 256>>>(c_g1, c_be1, h_g1, h_be1, w_g1, w_be1);

    k_conv2f<<<dim3(32, 32, 2), 256, SMEM>>>();

    k_prepA3n<<<dim3(256, 2), 256>>>(h_g2, h_be2, w_g2, w_be2);

    k_conv3f<<<dim3(8, 64, 2), 256, SMEM>>>(h_b3, w_b3);

    k_final<<<256, 256>>>(coef, out);
}